// round 12
// baseline (speedup 1.0000x reference)
#include <cuda_runtime.h>
#include <cuda_fp16.h>

#define BATCH 4
#define CIN   64
#define HID   128
#define PLANE 65536          // 256*256
#define NPIX  262144         // BATCH*PLANE
#define NELEM 33554432       // BATCH*HID*PLANE
#define OUT2  16777216       // BATCH*CIN*PLANE  (offset of prior_up in d_out)

// -------- scratch (static device globals: no allocation allowed) --------
__device__ float  g_ball[384];        // combined biases, index 3c+role
__device__ float  g_Aconst[HID];      // -exp(A_param)
__device__ float  g_prior[NPIX];      // clipped upsampled prior
__device__ __align__(16) __half g_Wh[64 * 384];   // fp16 proj weights [k][n], n=role*128+c, swizzled
__device__ __align__(16) __half g_Woh[128 * 64];  // fp16 W_out [k][co], swizzled
__device__ __half g_Abar[NELEM];
__device__ __half g_bx[NELEM];
__device__ __half g_sH[NELEM];        // H-scan result

__device__ __forceinline__ unsigned s2u(const void* p) {
    return (unsigned)__cvta_generic_to_shared(p);
}
__device__ __forceinline__ void ldsm_x4t(unsigned* r, unsigned addr) {
    asm volatile("ldmatrix.sync.aligned.m8n8.x4.trans.shared.b16 {%0,%1,%2,%3}, [%4];"
                 : "=r"(r[0]), "=r"(r[1]), "=r"(r[2]), "=r"(r[3]) : "r"(addr));
}
__device__ __forceinline__ void ldsm_x2t(unsigned* r, unsigned addr) {
    asm volatile("ldmatrix.sync.aligned.m8n8.x2.trans.shared.b16 {%0,%1}, [%2];"
                 : "=r"(r[0]), "=r"(r[1]) : "r"(addr));
}
__device__ __forceinline__ void mma16816(float* d, const unsigned* a, const unsigned* b) {
    asm volatile("mma.sync.aligned.m16n8k16.row.col.f32.f16.f16.f32 "
                 "{%0,%1,%2,%3},{%4,%5,%6,%7},{%8,%9},{%0,%1,%2,%3};"
                 : "+f"(d[0]), "+f"(d[1]), "+f"(d[2]), "+f"(d[3])
                 : "r"(a[0]), "r"(a[1]), "r"(a[2]), "r"(a[3]), "r"(b[0]), "r"(b[1]));
}

// ============================================================
// K_setup: blocks 0..129 = kpre, blocks 130.. = kprior
// ============================================================
__global__ __launch_bounds__(256) void ksetup(
    const float* __restrict__ W_in, const float* __restrict__ b_in,
    const float* __restrict__ W_delta, const float* __restrict__ b_delta,
    const float* __restrict__ W_B, const float* __restrict__ b_B,
    const float* __restrict__ A_param, const float* __restrict__ W_out,
    const float* __restrict__ prior, float* __restrict__ out2)
{
    if (blockIdx.x < 130) {
        int idx = blockIdx.x * 256 + threadIdx.x;
        if (idx < 384 * 64) {
            int r = idx >> 6, k = idx & 63;
            int c = r / 3, q = r - 3 * c;
            float v;
            if (q == 0) {
                v = W_in[c * 64 + k];
            } else {
                const float* Wm = (q == 1) ? W_delta : W_B;
                float s = 0.f;
                #pragma unroll 4
                for (int j = 0; j < 128; j++) s = fmaf(Wm[c * 128 + j], W_in[j * 64 + k], s);
                v = s;
            }
            int n = q * 128 + c;
            g_Wh[k * 384 + (((n >> 3) ^ (k & 7)) << 3) + (n & 7)] = __float2half(v);
        } else if (idx < 384 * 64 + 384) {
            int r = idx - 384 * 64;
            int c = r / 3, q = r - 3 * c;
            float v;
            if (q == 0) {
                v = b_in[c];
            } else {
                const float* Wm = (q == 1) ? W_delta : W_B;
                const float* bm = (q == 1) ? b_delta : b_B;
                float s = bm[c];
                #pragma unroll 4
                for (int j = 0; j < 128; j++) s = fmaf(Wm[c * 128 + j], b_in[j], s);
                v = s;
            }
            g_ball[r] = v;
        } else if (idx < 384 * 64 + 384 + HID) {
            int c = idx - (384 * 64 + 384);
            g_Aconst[c] = -expf(A_param[c]);
        } else if (idx < 384 * 64 + 384 + HID + 128 * 64) {
            int t = idx - (384 * 64 + 384 + HID);
            int k = t >> 6, co = t & 63;
            g_Woh[k * 64 + (((co >> 3) ^ (k & 7)) << 3) + (co & 7)] =
                __float2half(W_out[co * 128 + k]);
        }
        return;
    }
    int tid = (blockIdx.x - 130) * 256 + threadIdx.x;
    int bi = tid >> 16;
    int hw = tid & 65535;
    int oy = hw >> 8, ox = hw & 255;

    float fy = (float)(oy * 63) / 255.0f;
    float fx = (float)(ox * 63) / 255.0f;
    int y0 = (int)fy; int y1 = min(y0 + 1, 63);
    int x0 = (int)fx; int x1 = min(x0 + 1, 63);
    float wy = fy - (float)y0;
    float wx = fx - (float)x0;

    const float* p = prior + bi * 4096;
    float v00 = p[y0 * 64 + x0], v10 = p[y1 * 64 + x0];
    float v01 = p[y0 * 64 + x1], v11 = p[y1 * 64 + x1];
    float r0 = v00 * (1.f - wy) + v10 * wy;
    float r1 = v01 * (1.f - wy) + v11 * wy;
    float val = r0 * (1.f - wx) + r1 * wx;
    val = fminf(fmaxf(val, -1.f), 1.f);

    g_prior[tid] = val;
    out2[tid] = val;
}

// ============================================================
// K_proj: register-prefetched, 4 tiles/block, double-buffered sXc,
// ONE barrier per tile, direct sector-granular stores, 2 blocks/SM.
// smem bytes: sWh 49152 | sXc 2x8192 | sps 1024 | sball 1536 | sAc 512
// ============================================================
#define SMEM_KP 68608
#define KTILES  4

__global__ __launch_bounds__(512, 2) void kproj(
    const float* __restrict__ x,
    const float* __restrict__ lam_p,
    const float* __restrict__ alp_p)
{
    extern __shared__ char smc[];
    __half* sWh = (__half*)smc;
    __half* sXc = (__half*)(smc + 49152);           // 2 bufs x [c=64][px=64] swizzled
    float*  sps = (float*)(smc + 65536);            // [256]
    float*  sball = sps + 256;                      // [384]
    float*  sAc   = sball + 384;                    // [128]

    int tid = threadIdx.x;
    int pixB = blockIdx.x * (KTILES * 64);
    int bi = pixB >> 16;
    int hwB = pixB & 65535;
    const float* xg = x + (size_t)bi * CIN * PLANE + hwB;

    // weight staging (plain LDG, L2-resident after wave 1)
    {
        const uint4* gW = (const uint4*)g_Wh;
        uint4* sW = (uint4*)sWh;
        #pragma unroll
        for (int q = tid; q < 3072; q += 512) sW[q] = gW[q];
    }
    // constants — OVERLAPPING predicates: full coverage of every array
    if (tid < 256) sps[tid] = g_prior[pixB + tid];
    if (tid < 384) sball[tid] = g_ball[tid];
    if (tid < 128) sAc[tid] = g_Aconst[tid];

    // x mapping: q in [0,1024): c = q>>4, seg = q&15 -> 4 floats at px seg*4
    int q0 = tid, q1 = tid + 512;
    int c0 = q0 >> 4, s0 = q0 & 15;
    int c1 = q1 >> 4, s1 = q1 & 15;

    // preload tile 0
    float4 xr0 = *(const float4*)(xg + (size_t)c0 * PLANE + s0 * 4);
    float4 xr1 = *(const float4*)(xg + (size_t)c1 * PLANE + s1 * 4);

    int w = tid >> 5, lane = tid & 31;
    int wp = w & 7, jw = w >> 3;
    int lr = lane & 15;
    int kr = lane & 7, sel = lane >> 3;
    float lam = *lam_p;
    float alp = *alp_p;

    unsigned aBase = s2u(sXc);

    #pragma unroll 1
    for (int t = 0; t < KTILES; t++) {
        // store-convert registers -> k-major swizzled sXc buffer (t&1)
        {
            __half* buf = sXc + (t & 1) * 4096;
            __half2 h01 = __floats2half2_rn(xr0.x, xr0.y);
            __half2 h23 = __floats2half2_rn(xr0.z, xr0.w);
            uint2 u; u.x = *(unsigned*)&h01; u.y = *(unsigned*)&h23;
            *(uint2*)&buf[c0 * 64 + (((s0 >> 1) ^ (c0 & 7)) << 3) + (s0 & 1) * 4] = u;
            h01 = __floats2half2_rn(xr1.x, xr1.y);
            h23 = __floats2half2_rn(xr1.z, xr1.w);
            u.x = *(unsigned*)&h01; u.y = *(unsigned*)&h23;
            *(uint2*)&buf[c1 * 64 + (((s1 >> 1) ^ (c1 & 7)) << 3) + (s1 & 1) * 4] = u;
        }
        __syncthreads();    // conv(t) visible to all; also covers weights/consts on t=0

        // prefetch next tile into registers (consumed next iteration)
        if (t + 1 < KTILES) {
            const float* gt = xg + (t + 1) * 64;
            xr0 = *(const float4*)(gt + (size_t)c0 * PLANE + s0 * 4);
            xr1 = *(const float4*)(gt + (size_t)c1 * PLANE + s1 * 4);
        }

        // mma
        float acc[4][3][4];
        #pragma unroll
        for (int i = 0; i < 4; i++)
            #pragma unroll
            for (int j = 0; j < 3; j++)
                #pragma unroll
                for (int q = 0; q < 4; q++) acc[i][j][q] = 0.f;

        unsigned a0 = aBase + (t & 1) * 8192;
        #pragma unroll
        for (int kc = 0; kc < 4; kc++) {
            unsigned a[4][4];
            #pragma unroll
            for (int ma = 0; ma < 4; ma++) {
                int krow = kc * 16 + ((sel >> 1) << 3) + kr;
                int mcol = ma * 16 + ((sel & 1) << 3);
                unsigned addr = a0 + (krow * 64 + (((mcol >> 3) ^ (krow & 7)) << 3)) * 2;
                ldsm_x4t(a[ma], addr);
            }
            unsigned b[3][2];
            #pragma unroll
            for (int r3 = 0; r3 < 3; r3++) {
                int na = r3 * 16 + wp * 2 + jw;
                int k = kc * 16 + lr;
                int nb = na * 8;
                unsigned addr = s2u(&sWh[k * 384 + (((nb >> 3) ^ (k & 7)) << 3)]);
                ldsm_x2t(b[r3], addr);
            }
            #pragma unroll
            for (int ma = 0; ma < 4; ma++)
                #pragma unroll
                for (int r3 = 0; r3 < 3; r3++)
                    mma16816(acc[ma][r3], a[ma], b[r3]);
        }

        // epilogue: direct sector-granular global stores (no staging)
        size_t ob = (size_t)bi * HID * PLANE + hwB + t * 64;
        #pragma unroll
        for (int i = 0; i < 2; i++) {
            int c = wp * 16 + jw * 8 + (lane & 3) * 2 + i;
            float bin = sball[3 * c];
            float bdl = sball[3 * c + 1];
            float bbb = sball[3 * c + 2];
            float Ac  = sAc[c];
            size_t cb = ob + (size_t)c * PLANE;
            #pragma unroll
            for (int ma = 0; ma < 4; ma++) {
                #pragma unroll
                for (int rr = 0; rr < 2; rr++) {
                    int px = ma * 16 + (lane >> 2) + rr * 8;
                    int idx = rr * 2 + i;
                    float p = sps[t * 64 + px];
                    float xp   = acc[ma][0][idx] + bin;
                    float dpre = acc[ma][1][idx] + bdl + lam * p;
                    float delta = fmaxf(dpre, 0.f) + __logf(1.f + __expf(-fabsf(dpre)));
                    float bk = (acc[ma][2][idx] + bbb) * (1.f + alp * p);
                    g_Abar[cb + px] = __float2half(__expf(delta * Ac));
                    g_bx[cb + px]   = __float2half(delta * bk * xp);
                }
            }
        }
        // no second barrier: next conv writes the other sXc buffer
    }
}

// ============================================================
// K_scanH: block = 256 rows x 64-col strip of one plane. Single DRAM pass.
// ============================================================
#define SMEM_SH (65536 + 4096)

__global__ __launch_bounds__(256) void kscanH()
{
    extern __shared__ __half2 sh2[];
    __half2* sA2 = sh2;              // [256][32] half2
    __half2* sB2 = sh2 + 8192;
    float2* AcS  = (float2*)(sh2 + 16384);   // [8][32]
    float2* BcS  = AcS + 256;

    int tid = threadIdx.x;
    int blk = blockIdx.x;
    size_t gbase = (size_t)(blk >> 2) * PLANE + (size_t)(blk & 3) * 64;
    size_t gb2 = gbase >> 1;

    {
        const __half* gA = g_Abar + gbase;
        const __half* gB = g_bx + gbase;
        #pragma unroll
        for (int q = tid; q < 2048; q += 256) {
            int r = q >> 3, g = q & 7;
            *(uint4*)&sA2[r * 32 + g * 4] = *(const uint4*)&gA[(size_t)r * 256 + g * 8];
            *(uint4*)&sB2[r * 32 + g * 4] = *(const uint4*)&gB[(size_t)r * 256 + g * 8];
        }
    }
    __syncthreads();

    int col2 = tid & 31;
    int chunk = tid >> 5;
    int r0 = chunk * 32;

    float2 Ac = make_float2(1.f, 1.f), Bc = make_float2(0.f, 0.f);
    #pragma unroll 8
    for (int r = 0; r < 32; r++) {
        float2 a = __half22float2(sA2[(r0 + r) * 32 + col2]);
        float2 b = __half22float2(sB2[(r0 + r) * 32 + col2]);
        Bc.x = fmaf(a.x, Bc.x, b.x); Bc.y = fmaf(a.y, Bc.y, b.y);
        Ac.x *= a.x; Ac.y *= a.y;
    }
    AcS[tid] = Ac; BcS[tid] = Bc;
    __syncthreads();

    float2 h = make_float2(0.f, 0.f);
    for (int k = 0; k < chunk; k++) {
        float2 A = AcS[k * 32 + col2];
        float2 B = BcS[k * 32 + col2];
        h.x = fmaf(A.x, h.x, B.x); h.y = fmaf(A.y, h.y, B.y);
    }

    __half2* S2 = (__half2*)g_sH;
    #pragma unroll 8
    for (int r = 0; r < 32; r++) {
        float2 a = __half22float2(sA2[(r0 + r) * 32 + col2]);
        float2 b = __half22float2(sB2[(r0 + r) * 32 + col2]);
        h.x = fmaf(a.x, h.x, b.x); h.y = fmaf(a.y, h.y, b.y);
        S2[gb2 + (size_t)(r0 + r) * 128 + col2] = __floats2half2_rn(h.x, h.y);
    }
}

// ============================================================
// K_scanWout: FUSED W-scan + sum(sH) + output GEMM + direct residual store.
// ============================================================
#define SMEM_SWO (82176)

__device__ __forceinline__ void unpack8h(uint4 u, float* f) {
    float2 t;
    t = __half22float2(*(__half2*)&u.x); f[0] = t.x; f[1] = t.y;
    t = __half22float2(*(__half2*)&u.y); f[2] = t.x; f[3] = t.y;
    t = __half22float2(*(__half2*)&u.z); f[4] = t.x; f[5] = t.y;
    t = __half22float2(*(__half2*)&u.w); f[6] = t.x; f[7] = t.y;
}

__global__ __launch_bounds__(512, 2) void kscanWout(
    const float* __restrict__ x,
    const float* __restrict__ b_out,
    const float* __restrict__ gam_p,
    float* __restrict__ out)
{
    extern __shared__ __half sm[];
    __half* sS  = sm;                       // [k=128][px=256] swizzled (64KB)
    __half* sWo = sm + 32768;               // [k=128][co=64] swizzled (16KB)
    float* sbo  = (float*)(sm + 40960);     // [64]

    int tid = threadIdx.x;
    int w = tid >> 5, lane = tid & 31;
    int bi = blockIdx.x >> 8;
    int y  = blockIdx.x & 255;

    {
        const uint4* gW = (const uint4*)g_Woh;
        uint4* sW = (uint4*)sWo;
        #pragma unroll
        for (int q = tid; q < 1024; q += 512) sW[q] = gW[q];
    }
    if (tid < 64) sbo[tid] = b_out[tid];

    // ---- Phase 1: W-scan 8 channels per warp (pipelined loads) ----
    size_t base = ((size_t)(bi * HID + w * 8)) * PLANE + (size_t)y * 256 + lane * 8;
    uint4 ua = *(const uint4*)(g_Abar + base);
    uint4 ub = *(const uint4*)(g_bx + base);
    uint4 us = *(const uint4*)(g_sH + base);

    #pragma unroll 1
    for (int i = 0; i < 8; i++) {
        float a[8], b[8], s[8];
        unpack8h(ua, a); unpack8h(ub, b); unpack8h(us, s);
        if (i < 7) {
            size_t nb = base + (size_t)(i + 1) * PLANE;
            ua = *(const uint4*)(g_Abar + nb);
            ub = *(const uint4*)(g_bx + nb);
            us = *(const uint4*)(g_sH + nb);
        }

        float Ac = 1.f, Bc = 0.f;
        #pragma unroll
        for (int j = 0; j < 8; j++) {
            Bc = fmaf(a[j], Bc, b[j]);
            Ac = a[j] * Ac;
        }
        #pragma unroll
        for (int d = 1; d < 32; d <<= 1) {
            float Ap = __shfl_up_sync(0xffffffffu, Ac, d);
            float Bp = __shfl_up_sync(0xffffffffu, Bc, d);
            if (lane >= d) {
                Bc = fmaf(Ac, Bp, Bc);
                Ac = Ac * Ap;
            }
        }
        float hin = __shfl_up_sync(0xffffffffu, Bc, 1);
        if (lane == 0) hin = 0.f;

        float h = hin, r[8];
        #pragma unroll
        for (int j = 0; j < 8; j++) {
            h = fmaf(a[j], h, b[j]);
            r[j] = h + s[j];
        }
        int c = w * 8 + i;
        union { uint4 u; __half2 hh[4]; } o;
        o.hh[0] = __floats2half2_rn(r[0], r[1]);
        o.hh[1] = __floats2half2_rn(r[2], r[3]);
        o.hh[2] = __floats2half2_rn(r[4], r[5]);
        o.hh[3] = __floats2half2_rn(r[6], r[7]);
        *(uint4*)&sS[c * 256 + ((lane ^ (c & 7)) << 3)] = o.u;
    }
    __syncthreads();

    // ---- Phase 2: GEMM. Warp w owns m-atom w (16 px), all 8 co-atoms. ----
    float acc[8][4];
    #pragma unroll
    for (int j = 0; j < 8; j++)
        #pragma unroll
        for (int q = 0; q < 4; q++) acc[j][q] = 0.f;

    int kr = lane & 7, sel = lane >> 3;
    #pragma unroll
    for (int kc = 0; kc < 8; kc++) {
        unsigned a[4];
        {
            int krow = kc * 16 + ((sel >> 1) << 3) + kr;
            int mcol = w * 16 + ((sel & 1) << 3);
            unsigned addr = s2u(&sS[krow * 256 + (((mcol >> 3) ^ (krow & 7)) << 3)]);
            ldsm_x4t(a, addr);
        }
        #pragma unroll
        for (int jp = 0; jp < 4; jp++) {
            unsigned b4[4];
            int k = kc * 16 + (lane & 15);
            int cog = jp * 2 + (lane >> 4);
            unsigned addr = s2u(&sWo[k * 64 + ((cog ^ (k & 7)) << 3)]);
            ldsm_x4t(b4, addr);
            mma16816(acc[jp * 2], a, b4);
            mma16816(acc[jp * 2 + 1], a, b4 + 2);
        }
    }

    // ---- direct epilogue ----
    float gam = *gam_p;
    int px = w * 16 + (lane >> 2);
    size_t rowb = (size_t)bi * CIN * PLANE + (size_t)y * 256;
    #pragma unroll
    for (int na = 0; na < 8; na++) {
        int co = na * 8 + (lane & 3) * 2;
        float bo0 = sbo[co], bo1 = sbo[co + 1];
        size_t b0 = rowb + (size_t)co * PLANE + px;
        out[b0]             = fmaf(gam, acc[na][0] + bo0, x[b0]);
        out[b0 + PLANE]     = fmaf(gam, acc[na][1] + bo1, x[b0 + PLANE]);
        out[b0 + 8]         = fmaf(gam, acc[na][2] + bo0, x[b0 + 8]);
        out[b0 + PLANE + 8] = fmaf(gam, acc[na][3] + bo1, x[b0 + PLANE + 8]);
    }
}

// ============================================================
extern "C" void kernel_launch(void* const* d_in, const int* in_sizes, int n_in,
                              void* d_out, int out_size)
{
    const float* x       = (const float*)d_in[0];
    const float* prior   = (const float*)d_in[1];
    const float* W_in    = (const float*)d_in[2];
    const float* b_in    = (const float*)d_in[3];
    const float* W_out   = (const float*)d_in[4];
    const float* b_out   = (const float*)d_in[5];
    const float* W_delta = (const float*)d_in[6];
    const float* b_delta = (const float*)d_in[7];
    const float* W_B     = (const float*)d_in[8];
    const float* b_B     = (const float*)d_in[9];
    const float* A_param = (const float*)d_in[10];
    const float* lam     = (const float*)d_in[11];
    const float* alp     = (const float*)d_in[12];
    const float* gam     = (const float*)d_in[13];
    float* out = (float*)d_out;

    cudaFuncSetAttribute(kproj, cudaFuncAttributeMaxDynamicSharedMemorySize, SMEM_KP);
    cudaFuncSetAttribute(kscanH, cudaFuncAttributeMaxDynamicSharedMemorySize, SMEM_SH);
    cudaFuncSetAttribute(kscanWout, cudaFuncAttributeMaxDynamicSharedMemorySize, SMEM_SWO);

    ksetup<<<130 + NPIX / 256, 256>>>(W_in, b_in, W_delta, b_delta, W_B, b_B,
                                      A_param, W_out, prior, out + OUT2);
    kproj<<<NPIX / (KTILES * 64), 512, SMEM_KP>>>(x, lam, alp);
    kscanH<<<2048, 256, SMEM_SH>>>();
    kscanWout<<<BATCH * 256, 512, SMEM_SWO>>>(x, b_out, gam, out);
}

// round 13
// speedup vs baseline: 1.1968x; 1.1968x over previous
#include <cuda_runtime.h>
#include <cuda_fp16.h>

#define BATCH 4
#define CIN   64
#define HID   128
#define PLANE 65536          // 256*256
#define NPIX  262144         // BATCH*PLANE
#define NELEM 33554432       // BATCH*HID*PLANE
#define OUT2  16777216       // BATCH*CIN*PLANE  (offset of prior_up in d_out)

// -------- scratch (static device globals: no allocation allowed) --------
__device__ float  g_ball[384];        // combined biases, index 3c+role
__device__ float  g_Aconst[HID];      // -exp(A_param)
__device__ float  g_prior[NPIX];      // clipped upsampled prior
__device__ __align__(16) __half g_Wh[64 * 384];   // fp16 proj weights [k][n], n=role*128+c, swizzled
__device__ __align__(16) __half g_Woh[128 * 64];  // fp16 W_out [k][co], swizzled
__device__ __half g_Abar[NELEM];
__device__ __half g_bx[NELEM];
__device__ __half g_sH[NELEM];        // H-scan result

__device__ __forceinline__ unsigned s2u(const void* p) {
    return (unsigned)__cvta_generic_to_shared(p);
}
__device__ __forceinline__ void ldsm_x4t(unsigned* r, unsigned addr) {
    asm volatile("ldmatrix.sync.aligned.m8n8.x4.trans.shared.b16 {%0,%1,%2,%3}, [%4];"
                 : "=r"(r[0]), "=r"(r[1]), "=r"(r[2]), "=r"(r[3]) : "r"(addr));
}
__device__ __forceinline__ void ldsm_x2t(unsigned* r, unsigned addr) {
    asm volatile("ldmatrix.sync.aligned.m8n8.x2.trans.shared.b16 {%0,%1}, [%2];"
                 : "=r"(r[0]), "=r"(r[1]) : "r"(addr));
}
__device__ __forceinline__ void mma16816(float* d, const unsigned* a, const unsigned* b) {
    asm volatile("mma.sync.aligned.m16n8k16.row.col.f32.f16.f16.f32 "
                 "{%0,%1,%2,%3},{%4,%5,%6,%7},{%8,%9},{%0,%1,%2,%3};"
                 : "+f"(d[0]), "+f"(d[1]), "+f"(d[2]), "+f"(d[3])
                 : "r"(a[0]), "r"(a[1]), "r"(a[2]), "r"(a[3]), "r"(b[0]), "r"(b[1]));
}

// ============================================================
// K_setup: blocks 0..129 = kpre, blocks 130.. = kprior
// ============================================================
__global__ __launch_bounds__(256) void ksetup(
    const float* __restrict__ W_in, const float* __restrict__ b_in,
    const float* __restrict__ W_delta, const float* __restrict__ b_delta,
    const float* __restrict__ W_B, const float* __restrict__ b_B,
    const float* __restrict__ A_param, const float* __restrict__ W_out,
    const float* __restrict__ prior, float* __restrict__ out2)
{
    if (blockIdx.x < 130) {
        int idx = blockIdx.x * 256 + threadIdx.x;
        if (idx < 384 * 64) {
            int r = idx >> 6, k = idx & 63;
            int c = r / 3, q = r - 3 * c;
            float v;
            if (q == 0) {
                v = W_in[c * 64 + k];
            } else {
                const float* Wm = (q == 1) ? W_delta : W_B;
                float s = 0.f;
                #pragma unroll 4
                for (int j = 0; j < 128; j++) s = fmaf(Wm[c * 128 + j], W_in[j * 64 + k], s);
                v = s;
            }
            int n = q * 128 + c;
            g_Wh[k * 384 + (((n >> 3) ^ (k & 7)) << 3) + (n & 7)] = __float2half(v);
        } else if (idx < 384 * 64 + 384) {
            int r = idx - 384 * 64;
            int c = r / 3, q = r - 3 * c;
            float v;
            if (q == 0) {
                v = b_in[c];
            } else {
                const float* Wm = (q == 1) ? W_delta : W_B;
                const float* bm = (q == 1) ? b_delta : b_B;
                float s = bm[c];
                #pragma unroll 4
                for (int j = 0; j < 128; j++) s = fmaf(Wm[c * 128 + j], b_in[j], s);
                v = s;
            }
            g_ball[r] = v;
        } else if (idx < 384 * 64 + 384 + HID) {
            int c = idx - (384 * 64 + 384);
            g_Aconst[c] = -expf(A_param[c]);
        } else if (idx < 384 * 64 + 384 + HID + 128 * 64) {
            int t = idx - (384 * 64 + 384 + HID);
            int k = t >> 6, co = t & 63;
            g_Woh[k * 64 + (((co >> 3) ^ (k & 7)) << 3) + (co & 7)] =
                __float2half(W_out[co * 128 + k]);
        }
        return;
    }
    int tid = (blockIdx.x - 130) * 256 + threadIdx.x;
    int bi = tid >> 16;
    int hw = tid & 65535;
    int oy = hw >> 8, ox = hw & 255;

    float fy = (float)(oy * 63) / 255.0f;
    float fx = (float)(ox * 63) / 255.0f;
    int y0 = (int)fy; int y1 = min(y0 + 1, 63);
    int x0 = (int)fx; int x1 = min(x0 + 1, 63);
    float wy = fy - (float)y0;
    float wx = fx - (float)x0;

    const float* p = prior + bi * 4096;
    float v00 = p[y0 * 64 + x0], v10 = p[y1 * 64 + x0];
    float v01 = p[y0 * 64 + x1], v11 = p[y1 * 64 + x1];
    float r0 = v00 * (1.f - wy) + v10 * wy;
    float r1 = v01 * (1.f - wy) + v11 * wy;
    float val = r0 * (1.f - wx) + r1 * wx;
    val = fminf(fmaxf(val, -1.f), 1.f);

    g_prior[tid] = val;
    out2[tid] = val;
}

// ============================================================
// K_proj: 1024 threads / 32 warps, 24 accs/thread (no spills),
// 4 tiles/block, double-buffered sXc, ONE barrier per tile,
// direct sector-granular stores.
// Warp map: mh = w>>4 picks m-atom pair; (wp,jw) = ((w&15)&7, (w&15)>>3).
// smem bytes: sWh 49152 | sXc 2x8192 | sps 1024 | sball 1536 | sAc 512
// ============================================================
#define SMEM_KP 68608
#define KTILES  4

__global__ __launch_bounds__(1024) void kproj(
    const float* __restrict__ x,
    const float* __restrict__ lam_p,
    const float* __restrict__ alp_p)
{
    extern __shared__ char smc[];
    __half* sWh = (__half*)smc;
    __half* sXc = (__half*)(smc + 49152);           // 2 bufs x [c=64][px=64] swizzled
    float*  sps = (float*)(smc + 65536);            // [256]
    float*  sball = sps + 256;                      // [384]
    float*  sAc   = sball + 384;                    // [128]

    int tid = threadIdx.x;
    int pixB = blockIdx.x * (KTILES * 64);
    int bi = pixB >> 16;
    int hwB = pixB & 65535;
    const float* xg = x + (size_t)bi * CIN * PLANE + hwB;

    // weight staging (plain LDG, L2-resident after wave 1)
    {
        const uint4* gW = (const uint4*)g_Wh;
        uint4* sW = (uint4*)sWh;
        #pragma unroll
        for (int q = tid; q < 3072; q += 1024) sW[q] = gW[q];
    }
    // constants — OVERLAPPING predicates: full coverage of every array
    if (tid < 256) sps[tid] = g_prior[pixB + tid];
    if (tid < 384) sball[tid] = g_ball[tid];
    if (tid < 128) sAc[tid] = g_Aconst[tid];

    // x mapping: tid in [0,1024): c = tid>>4, s = tid&15 -> 4 floats at px s*4
    int c0 = tid >> 4, s0 = tid & 15;

    // preload tile 0
    float4 xr0 = *(const float4*)(xg + (size_t)c0 * PLANE + s0 * 4);

    int w = tid >> 5, lane = tid & 31;
    int mh = w >> 4;              // m-atom pair: {2mh, 2mh+1}
    int wq = w & 15;
    int wp = wq & 7, jw = wq >> 3;
    int lr = lane & 15;
    int kr = lane & 7, sel = lane >> 3;
    float lam = *lam_p;
    float alp = *alp_p;

    unsigned aBase = s2u(sXc);

    #pragma unroll 1
    for (int t = 0; t < KTILES; t++) {
        // store-convert register -> k-major swizzled sXc buffer (t&1)
        {
            __half* buf = sXc + (t & 1) * 4096;
            __half2 h01 = __floats2half2_rn(xr0.x, xr0.y);
            __half2 h23 = __floats2half2_rn(xr0.z, xr0.w);
            uint2 u; u.x = *(unsigned*)&h01; u.y = *(unsigned*)&h23;
            *(uint2*)&buf[c0 * 64 + (((s0 >> 1) ^ (c0 & 7)) << 3) + (s0 & 1) * 4] = u;
        }
        __syncthreads();    // conv(t) visible; also covers weights/consts on t=0

        // prefetch next tile into registers (consumed next iteration)
        if (t + 1 < KTILES) {
            const float* gt = xg + (t + 1) * 64;
            xr0 = *(const float4*)(gt + (size_t)c0 * PLANE + s0 * 4);
        }

        // mma: 2 m-atoms x 3 roles = 6 mma, 24 accs
        float acc[2][3][4];
        #pragma unroll
        for (int i = 0; i < 2; i++)
            #pragma unroll
            for (int j = 0; j < 3; j++)
                #pragma unroll
                for (int q = 0; q < 4; q++) acc[i][j][q] = 0.f;

        unsigned a0 = aBase + (t & 1) * 8192;
        #pragma unroll
        for (int kc = 0; kc < 4; kc++) {
            unsigned a[2][4];
            #pragma unroll
            for (int mm = 0; mm < 2; mm++) {
                int ma = mh * 2 + mm;
                int krow = kc * 16 + ((sel >> 1) << 3) + kr;
                int mcol = ma * 16 + ((sel & 1) << 3);
                unsigned addr = a0 + (krow * 64 + (((mcol >> 3) ^ (krow & 7)) << 3)) * 2;
                ldsm_x4t(a[mm], addr);
            }
            unsigned b[3][2];
            #pragma unroll
            for (int r3 = 0; r3 < 3; r3++) {
                int na = r3 * 16 + wp * 2 + jw;
                int k = kc * 16 + lr;
                int nb = na * 8;
                unsigned addr = s2u(&sWh[k * 384 + (((nb >> 3) ^ (k & 7)) << 3)]);
                ldsm_x2t(b[r3], addr);
            }
            #pragma unroll
            for (int mm = 0; mm < 2; mm++)
                #pragma unroll
                for (int r3 = 0; r3 < 3; r3++)
                    mma16816(acc[mm][r3], a[mm], b[r3]);
        }

        // epilogue: direct sector-granular global stores (no staging)
        size_t ob = (size_t)bi * HID * PLANE + hwB + t * 64;
        #pragma unroll
        for (int i = 0; i < 2; i++) {
            int c = wp * 16 + jw * 8 + (lane & 3) * 2 + i;
            float bin = sball[3 * c];
            float bdl = sball[3 * c + 1];
            float bbb = sball[3 * c + 2];
            float Ac  = sAc[c];
            size_t cb = ob + (size_t)c * PLANE;
            #pragma unroll
            for (int mm = 0; mm < 2; mm++) {
                int ma = mh * 2 + mm;
                #pragma unroll
                for (int rr = 0; rr < 2; rr++) {
                    int px = ma * 16 + (lane >> 2) + rr * 8;
                    int idx = rr * 2 + i;
                    float p = sps[t * 64 + px];
                    float xp   = acc[mm][0][idx] + bin;
                    float dpre = acc[mm][1][idx] + bdl + lam * p;
                    float delta = fmaxf(dpre, 0.f) + __logf(1.f + __expf(-fabsf(dpre)));
                    float bk = (acc[mm][2][idx] + bbb) * (1.f + alp * p);
                    g_Abar[cb + px] = __float2half(__expf(delta * Ac));
                    g_bx[cb + px]   = __float2half(delta * bk * xp);
                }
            }
        }
        // no second barrier: next conv writes the other sXc buffer
    }
}

// ============================================================
// K_scanH: block = 256 rows x 64-col strip of one plane. Single DRAM pass.
// ============================================================
#define SMEM_SH (65536 + 4096)

__global__ __launch_bounds__(256) void kscanH()
{
    extern __shared__ __half2 sh2[];
    __half2* sA2 = sh2;              // [256][32] half2
    __half2* sB2 = sh2 + 8192;
    float2* AcS  = (float2*)(sh2 + 16384);   // [8][32]
    float2* BcS  = AcS + 256;

    int tid = threadIdx.x;
    int blk = blockIdx.x;
    size_t gbase = (size_t)(blk >> 2) * PLANE + (size_t)(blk & 3) * 64;
    size_t gb2 = gbase >> 1;

    {
        const __half* gA = g_Abar + gbase;
        const __half* gB = g_bx + gbase;
        #pragma unroll
        for (int q = tid; q < 2048; q += 256) {
            int r = q >> 3, g = q & 7;
            *(uint4*)&sA2[r * 32 + g * 4] = *(const uint4*)&gA[(size_t)r * 256 + g * 8];
            *(uint4*)&sB2[r * 32 + g * 4] = *(const uint4*)&gB[(size_t)r * 256 + g * 8];
        }
    }
    __syncthreads();

    int col2 = tid & 31;
    int chunk = tid >> 5;
    int r0 = chunk * 32;

    float2 Ac = make_float2(1.f, 1.f), Bc = make_float2(0.f, 0.f);
    #pragma unroll 8
    for (int r = 0; r < 32; r++) {
        float2 a = __half22float2(sA2[(r0 + r) * 32 + col2]);
        float2 b = __half22float2(sB2[(r0 + r) * 32 + col2]);
        Bc.x = fmaf(a.x, Bc.x, b.x); Bc.y = fmaf(a.y, Bc.y, b.y);
        Ac.x *= a.x; Ac.y *= a.y;
    }
    AcS[tid] = Ac; BcS[tid] = Bc;
    __syncthreads();

    float2 h = make_float2(0.f, 0.f);
    for (int k = 0; k < chunk; k++) {
        float2 A = AcS[k * 32 + col2];
        float2 B = BcS[k * 32 + col2];
        h.x = fmaf(A.x, h.x, B.x); h.y = fmaf(A.y, h.y, B.y);
    }

    __half2* S2 = (__half2*)g_sH;
    #pragma unroll 8
    for (int r = 0; r < 32; r++) {
        float2 a = __half22float2(sA2[(r0 + r) * 32 + col2]);
        float2 b = __half22float2(sB2[(r0 + r) * 32 + col2]);
        h.x = fmaf(a.x, h.x, b.x); h.y = fmaf(a.y, h.y, b.y);
        S2[gb2 + (size_t)(r0 + r) * 128 + col2] = __floats2half2_rn(h.x, h.y);
    }
}

// ============================================================
// K_scanWout: FUSED W-scan + sum(sH) + output GEMM + direct residual store.
// ============================================================
#define SMEM_SWO (82176)

__device__ __forceinline__ void unpack8h(uint4 u, float* f) {
    float2 t;
    t = __half22float2(*(__half2*)&u.x); f[0] = t.x; f[1] = t.y;
    t = __half22float2(*(__half2*)&u.y); f[2] = t.x; f[3] = t.y;
    t = __half22float2(*(__half2*)&u.z); f[4] = t.x; f[5] = t.y;
    t = __half22float2(*(__half2*)&u.w); f[6] = t.x; f[7] = t.y;
}

__global__ __launch_bounds__(512, 2) void kscanWout(
    const float* __restrict__ x,
    const float* __restrict__ b_out,
    const float* __restrict__ gam_p,
    float* __restrict__ out)
{
    extern __shared__ __half sm[];
    __half* sS  = sm;                       // [k=128][px=256] swizzled (64KB)
    __half* sWo = sm + 32768;               // [k=128][co=64] swizzled (16KB)
    float* sbo  = (float*)(sm + 40960);     // [64]

    int tid = threadIdx.x;
    int w = tid >> 5, lane = tid & 31;
    int bi = blockIdx.x >> 8;
    int y  = blockIdx.x & 255;

    {
        const uint4* gW = (const uint4*)g_Woh;
        uint4* sW = (uint4*)sWo;
        #pragma unroll
        for (int q = tid; q < 1024; q += 512) sW[q] = gW[q];
    }
    if (tid < 64) sbo[tid] = b_out[tid];

    // ---- Phase 1: W-scan 8 channels per warp (pipelined loads) ----
    size_t base = ((size_t)(bi * HID + w * 8)) * PLANE + (size_t)y * 256 + lane * 8;
    uint4 ua = *(const uint4*)(g_Abar + base);
    uint4 ub = *(const uint4*)(g_bx + base);
    uint4 us = *(const uint4*)(g_sH + base);

    #pragma unroll 1
    for (int i = 0; i < 8; i++) {
        float a[8], b[8], s[8];
        unpack8h(ua, a); unpack8h(ub, b); unpack8h(us, s);
        if (i < 7) {
            size_t nb = base + (size_t)(i + 1) * PLANE;
            ua = *(const uint4*)(g_Abar + nb);
            ub = *(const uint4*)(g_bx + nb);
            us = *(const uint4*)(g_sH + nb);
        }

        float Ac = 1.f, Bc = 0.f;
        #pragma unroll
        for (int j = 0; j < 8; j++) {
            Bc = fmaf(a[j], Bc, b[j]);
            Ac = a[j] * Ac;
        }
        #pragma unroll
        for (int d = 1; d < 32; d <<= 1) {
            float Ap = __shfl_up_sync(0xffffffffu, Ac, d);
            float Bp = __shfl_up_sync(0xffffffffu, Bc, d);
            if (lane >= d) {
                Bc = fmaf(Ac, Bp, Bc);
                Ac = Ac * Ap;
            }
        }
        float hin = __shfl_up_sync(0xffffffffu, Bc, 1);
        if (lane == 0) hin = 0.f;

        float h = hin, r[8];
        #pragma unroll
        for (int j = 0; j < 8; j++) {
            h = fmaf(a[j], h, b[j]);
            r[j] = h + s[j];
        }
        int c = w * 8 + i;
        union { uint4 u; __half2 hh[4]; } o;
        o.hh[0] = __floats2half2_rn(r[0], r[1]);
        o.hh[1] = __floats2half2_rn(r[2], r[3]);
        o.hh[2] = __floats2half2_rn(r[4], r[5]);
        o.hh[3] = __floats2half2_rn(r[6], r[7]);
        *(uint4*)&sS[c * 256 + ((lane ^ (c & 7)) << 3)] = o.u;
    }
    __syncthreads();

    // ---- Phase 2: GEMM. Warp w owns m-atom w (16 px), all 8 co-atoms. ----
    float acc[8][4];
    #pragma unroll
    for (int j = 0; j < 8; j++)
        #pragma unroll
        for (int q = 0; q < 4; q++) acc[j][q] = 0.f;

    int kr = lane & 7, sel = lane >> 3;
    #pragma unroll
    for (int kc = 0; kc < 8; kc++) {
        unsigned a[4];
        {
            int krow = kc * 16 + ((sel >> 1) << 3) + kr;
            int mcol = w * 16 + ((sel & 1) << 3);
            unsigned addr = s2u(&sS[krow * 256 + (((mcol >> 3) ^ (krow & 7)) << 3)]);
            ldsm_x4t(a, addr);
        }
        #pragma unroll
        for (int jp = 0; jp < 4; jp++) {
            unsigned b4[4];
            int k = kc * 16 + (lane & 15);
            int cog = jp * 2 + (lane >> 4);
            unsigned addr = s2u(&sWo[k * 64 + ((cog ^ (k & 7)) << 3)]);
            ldsm_x4t(b4, addr);
            mma16816(acc[jp * 2], a, b4);
            mma16816(acc[jp * 2 + 1], a, b4 + 2);
        }
    }

    // ---- direct epilogue ----
    float gam = *gam_p;
    int px = w * 16 + (lane >> 2);
    size_t rowb = (size_t)bi * CIN * PLANE + (size_t)y * 256;
    #pragma unroll
    for (int na = 0; na < 8; na++) {
        int co = na * 8 + (lane & 3) * 2;
        float bo0 = sbo[co], bo1 = sbo[co + 1];
        size_t b0 = rowb + (size_t)co * PLANE + px;
        out[b0]             = fmaf(gam, acc[na][0] + bo0, x[b0]);
        out[b0 + PLANE]     = fmaf(gam, acc[na][1] + bo1, x[b0 + PLANE]);
        out[b0 + 8]         = fmaf(gam, acc[na][2] + bo0, x[b0 + 8]);
        out[b0 + PLANE + 8] = fmaf(gam, acc[na][3] + bo1, x[b0 + PLANE + 8]);
    }
}

// ============================================================
extern "C" void kernel_launch(void* const* d_in, const int* in_sizes, int n_in,
                              void* d_out, int out_size)
{
    const float* x       = (const float*)d_in[0];
    const float* prior   = (const float*)d_in[1];
    const float* W_in    = (const float*)d_in[2];
    const float* b_in    = (const float*)d_in[3];
    const float* W_out   = (const float*)d_in[4];
    const float* b_out   = (const float*)d_in[5];
    const float* W_delta = (const float*)d_in[6];
    const float* b_delta = (const float*)d_in[7];
    const float* W_B     = (const float*)d_in[8];
    const float* b_B     = (const float*)d_in[9];
    const float* A_param = (const float*)d_in[10];
    const float* lam     = (const float*)d_in[11];
    const float* alp     = (const float*)d_in[12];
    const float* gam     = (const float*)d_in[13];
    float* out = (float*)d_out;

    cudaFuncSetAttribute(kproj, cudaFuncAttributeMaxDynamicSharedMemorySize, SMEM_KP);
    cudaFuncSetAttribute(kscanH, cudaFuncAttributeMaxDynamicSharedMemorySize, SMEM_SH);
    cudaFuncSetAttribute(kscanWout, cudaFuncAttributeMaxDynamicSharedMemorySize, SMEM_SWO);

    ksetup<<<130 + NPIX / 256, 256>>>(W_in, b_in, W_delta, b_delta, W_B, b_B,
                                      A_param, W_out, prior, out + OUT2);
    kproj<<<NPIX / (KTILES * 64), 1024, SMEM_KP>>>(x, lam, alp);
    kscanH<<<2048, 256, SMEM_SH>>>();
    kscanWout<<<BATCH * 256, 512, SMEM_SWO>>>(x, b_out, gam, out);
}

// round 14
// speedup vs baseline: 1.3662x; 1.1415x over previous
#include <cuda_runtime.h>
#include <cuda_fp16.h>

#define BATCH 4
#define CIN   64
#define HID   128
#define PLANE 65536          // 256*256
#define NPIX  262144         // BATCH*PLANE
#define NELEM 33554432       // BATCH*HID*PLANE
#define OUT2  16777216       // BATCH*CIN*PLANE  (offset of prior_up in d_out)

// -------- scratch (static device globals: no allocation allowed) --------
__device__ float  g_ball[384];        // combined biases, index 3c+role
__device__ float  g_Aconst[HID];      // -exp(A_param)
__device__ float  g_prior[NPIX];      // clipped upsampled prior
__device__ __align__(16) __half g_Wh[64 * 384];   // fp16 proj weights [k][n], n=role*128+c, swizzled
__device__ __align__(16) __half g_Woh[128 * 64];  // fp16 W_out [k][co], swizzled
__device__ __align__(16) __half2 g_AB[NELEM];     // interleaved (A_bar, bx) per pixel
__device__ __half g_sH[NELEM];        // H-scan result

__device__ __forceinline__ unsigned s2u(const void* p) {
    return (unsigned)__cvta_generic_to_shared(p);
}
__device__ __forceinline__ void ldsm_x4t(unsigned* r, unsigned addr) {
    asm volatile("ldmatrix.sync.aligned.m8n8.x4.trans.shared.b16 {%0,%1,%2,%3}, [%4];"
                 : "=r"(r[0]), "=r"(r[1]), "=r"(r[2]), "=r"(r[3]) : "r"(addr));
}
__device__ __forceinline__ void ldsm_x2t(unsigned* r, unsigned addr) {
    asm volatile("ldmatrix.sync.aligned.m8n8.x2.trans.shared.b16 {%0,%1}, [%2];"
                 : "=r"(r[0]), "=r"(r[1]) : "r"(addr));
}
__device__ __forceinline__ void mma16816(float* d, const unsigned* a, const unsigned* b) {
    asm volatile("mma.sync.aligned.m16n8k16.row.col.f32.f16.f16.f32 "
                 "{%0,%1,%2,%3},{%4,%5,%6,%7},{%8,%9},{%0,%1,%2,%3};"
                 : "+f"(d[0]), "+f"(d[1]), "+f"(d[2]), "+f"(d[3])
                 : "r"(a[0]), "r"(a[1]), "r"(a[2]), "r"(a[3]), "r"(b[0]), "r"(b[1]));
}

// ============================================================
// K_setup: blocks 0..129 = kpre, blocks 130.. = kprior
// ============================================================
__global__ __launch_bounds__(256) void ksetup(
    const float* __restrict__ W_in, const float* __restrict__ b_in,
    const float* __restrict__ W_delta, const float* __restrict__ b_delta,
    const float* __restrict__ W_B, const float* __restrict__ b_B,
    const float* __restrict__ A_param, const float* __restrict__ W_out,
    const float* __restrict__ prior, float* __restrict__ out2)
{
    if (blockIdx.x < 130) {
        int idx = blockIdx.x * 256 + threadIdx.x;
        if (idx < 384 * 64) {
            int r = idx >> 6, k = idx & 63;
            int c = r / 3, q = r - 3 * c;
            float v;
            if (q == 0) {
                v = W_in[c * 64 + k];
            } else {
                const float* Wm = (q == 1) ? W_delta : W_B;
                float s = 0.f;
                #pragma unroll 4
                for (int j = 0; j < 128; j++) s = fmaf(Wm[c * 128 + j], W_in[j * 64 + k], s);
                v = s;
            }
            int n = q * 128 + c;
            g_Wh[k * 384 + (((n >> 3) ^ (k & 7)) << 3) + (n & 7)] = __float2half(v);
        } else if (idx < 384 * 64 + 384) {
            int r = idx - 384 * 64;
            int c = r / 3, q = r - 3 * c;
            float v;
            if (q == 0) {
                v = b_in[c];
            } else {
                const float* Wm = (q == 1) ? W_delta : W_B;
                const float* bm = (q == 1) ? b_delta : b_B;
                float s = bm[c];
                #pragma unroll 4
                for (int j = 0; j < 128; j++) s = fmaf(Wm[c * 128 + j], b_in[j], s);
                v = s;
            }
            g_ball[r] = v;
        } else if (idx < 384 * 64 + 384 + HID) {
            int c = idx - (384 * 64 + 384);
            g_Aconst[c] = -expf(A_param[c]);
        } else if (idx < 384 * 64 + 384 + HID + 128 * 64) {
            int t = idx - (384 * 64 + 384 + HID);
            int k = t >> 6, co = t & 63;
            g_Woh[k * 64 + (((co >> 3) ^ (k & 7)) << 3) + (co & 7)] =
                __float2half(W_out[co * 128 + k]);
        }
        return;
    }
    int tid = (blockIdx.x - 130) * 256 + threadIdx.x;
    int bi = tid >> 16;
    int hw = tid & 65535;
    int oy = hw >> 8, ox = hw & 255;

    float fy = (float)(oy * 63) / 255.0f;
    float fx = (float)(ox * 63) / 255.0f;
    int y0 = (int)fy; int y1 = min(y0 + 1, 63);
    int x0 = (int)fx; int x1 = min(x0 + 1, 63);
    float wy = fy - (float)y0;
    float wx = fx - (float)x0;

    const float* p = prior + bi * 4096;
    float v00 = p[y0 * 64 + x0], v10 = p[y1 * 64 + x0];
    float v01 = p[y0 * 64 + x1], v11 = p[y1 * 64 + x1];
    float r0 = v00 * (1.f - wy) + v10 * wy;
    float r1 = v01 * (1.f - wy) + v11 * wy;
    float val = r0 * (1.f - wx) + r1 * wx;
    val = fminf(fmaxf(val, -1.f), 1.f);

    g_prior[tid] = val;
    out2[tid] = val;
}

// ============================================================
// K_proj: 512 threads (R10 config), 4 tiles/block, double-buffered sXc,
// ONE barrier per tile; epilogue stores interleaved half2 (A,b) ->
// 32B-sector-aligned runs.
// smem bytes: sWh 49152 | sXc 2x8192 | sps 1024 | sball 1536 | sAc 512
// ============================================================
#define SMEM_KP 68608
#define KTILES  4

__global__ __launch_bounds__(512) void kproj(
    const float* __restrict__ x,
    const float* __restrict__ lam_p,
    const float* __restrict__ alp_p)
{
    extern __shared__ char smc[];
    __half* sWh = (__half*)smc;
    __half* sXc = (__half*)(smc + 49152);           // 2 bufs x [c=64][px=64] swizzled
    float*  sps = (float*)(smc + 65536);            // [256]
    float*  sball = sps + 256;                      // [384]
    float*  sAc   = sball + 384;                    // [128]

    int tid = threadIdx.x;
    int pixB = blockIdx.x * (KTILES * 64);
    int bi = pixB >> 16;
    int hwB = pixB & 65535;
    const float* xg = x + (size_t)bi * CIN * PLANE + hwB;

    // weight staging (plain LDG, L2-resident after wave 1)
    {
        const uint4* gW = (const uint4*)g_Wh;
        uint4* sW = (uint4*)sWh;
        #pragma unroll
        for (int q = tid; q < 3072; q += 512) sW[q] = gW[q];
    }
    // constants — OVERLAPPING predicates: full coverage of every array
    if (tid < 256) sps[tid] = g_prior[pixB + tid];
    if (tid < 384) sball[tid] = g_ball[tid];
    if (tid < 128) sAc[tid] = g_Aconst[tid];

    // x mapping: q in [0,1024): c = q>>4, seg = q&15 -> 4 floats at px seg*4
    int q0 = tid, q1 = tid + 512;
    int c0 = q0 >> 4, s0 = q0 & 15;
    int c1 = q1 >> 4, s1 = q1 & 15;

    // preload tile 0
    float4 xr0 = *(const float4*)(xg + (size_t)c0 * PLANE + s0 * 4);
    float4 xr1 = *(const float4*)(xg + (size_t)c1 * PLANE + s1 * 4);

    int w = tid >> 5, lane = tid & 31;
    int wp = w & 7, jw = w >> 3;
    int lr = lane & 15;
    int kr = lane & 7, sel = lane >> 3;
    float lam = *lam_p;
    float alp = *alp_p;

    unsigned aBase = s2u(sXc);

    #pragma unroll 1
    for (int t = 0; t < KTILES; t++) {
        // store-convert registers -> k-major swizzled sXc buffer (t&1)
        {
            __half* buf = sXc + (t & 1) * 4096;
            __half2 h01 = __floats2half2_rn(xr0.x, xr0.y);
            __half2 h23 = __floats2half2_rn(xr0.z, xr0.w);
            uint2 u; u.x = *(unsigned*)&h01; u.y = *(unsigned*)&h23;
            *(uint2*)&buf[c0 * 64 + (((s0 >> 1) ^ (c0 & 7)) << 3) + (s0 & 1) * 4] = u;
            h01 = __floats2half2_rn(xr1.x, xr1.y);
            h23 = __floats2half2_rn(xr1.z, xr1.w);
            u.x = *(unsigned*)&h01; u.y = *(unsigned*)&h23;
            *(uint2*)&buf[c1 * 64 + (((s1 >> 1) ^ (c1 & 7)) << 3) + (s1 & 1) * 4] = u;
        }
        __syncthreads();    // conv(t) visible to all; also covers weights/consts on t=0

        // prefetch next tile into registers (consumed next iteration)
        if (t + 1 < KTILES) {
            const float* gt = xg + (t + 1) * 64;
            xr0 = *(const float4*)(gt + (size_t)c0 * PLANE + s0 * 4);
            xr1 = *(const float4*)(gt + (size_t)c1 * PLANE + s1 * 4);
        }

        // mma
        float acc[4][3][4];
        #pragma unroll
        for (int i = 0; i < 4; i++)
            #pragma unroll
            for (int j = 0; j < 3; j++)
                #pragma unroll
                for (int q = 0; q < 4; q++) acc[i][j][q] = 0.f;

        unsigned a0 = aBase + (t & 1) * 8192;
        #pragma unroll
        for (int kc = 0; kc < 4; kc++) {
            unsigned a[4][4];
            #pragma unroll
            for (int ma = 0; ma < 4; ma++) {
                int krow = kc * 16 + ((sel >> 1) << 3) + kr;
                int mcol = ma * 16 + ((sel & 1) << 3);
                unsigned addr = a0 + (krow * 64 + (((mcol >> 3) ^ (krow & 7)) << 3)) * 2;
                ldsm_x4t(a[ma], addr);
            }
            unsigned b[3][2];
            #pragma unroll
            for (int r3 = 0; r3 < 3; r3++) {
                int na = r3 * 16 + wp * 2 + jw;
                int k = kc * 16 + lr;
                int nb = na * 8;
                unsigned addr = s2u(&sWh[k * 384 + (((nb >> 3) ^ (k & 7)) << 3)]);
                ldsm_x2t(b[r3], addr);
            }
            #pragma unroll
            for (int ma = 0; ma < 4; ma++)
                #pragma unroll
                for (int r3 = 0; r3 < 3; r3++)
                    mma16816(acc[ma][r3], a[ma], b[r3]);
        }

        // epilogue: direct interleaved half2 stores (full 32B sector runs)
        size_t ob = (size_t)bi * HID * PLANE + hwB + t * 64;
        #pragma unroll
        for (int i = 0; i < 2; i++) {
            int c = wp * 16 + jw * 8 + (lane & 3) * 2 + i;
            float bin = sball[3 * c];
            float bdl = sball[3 * c + 1];
            float bbb = sball[3 * c + 2];
            float Ac  = sAc[c];
            size_t cb = ob + (size_t)c * PLANE;
            #pragma unroll
            for (int ma = 0; ma < 4; ma++) {
                #pragma unroll
                for (int rr = 0; rr < 2; rr++) {
                    int px = ma * 16 + (lane >> 2) + rr * 8;
                    int idx = rr * 2 + i;
                    float p = sps[t * 64 + px];
                    float xp   = acc[ma][0][idx] + bin;
                    float dpre = acc[ma][1][idx] + bdl + lam * p;
                    float delta = fmaxf(dpre, 0.f) + __logf(1.f + __expf(-fabsf(dpre)));
                    float bk = (acc[ma][2][idx] + bbb) * (1.f + alp * p);
                    g_AB[cb + px] = __floats2half2_rn(__expf(delta * Ac), delta * bk * xp);
                }
            }
        }
        // no second barrier: next conv writes the other sXc buffer
    }
}

// ============================================================
// K_scanH: block = 256 rows x 64-col strip of one plane. Single DRAM pass.
// Loads interleaved (A,b) pairs from g_AB into smem [256][64] half2.
// ============================================================
#define SMEM_SH (65536 + 4096)

__global__ __launch_bounds__(256) void kscanH()
{
    extern __shared__ __half2 sh2[];          // sAB[256][64] (A,b) pairs
    float2* AcS  = (float2*)(sh2 + 16384);    // [8][32]
    float2* BcS  = AcS + 256;

    int tid = threadIdx.x;
    int blk = blockIdx.x;
    size_t gbase = (size_t)(blk >> 2) * PLANE + (size_t)(blk & 3) * 64;   // px index
    const __half2* gAB = g_AB + gbase;

    #pragma unroll
    for (int q = tid; q < 4096; q += 256) {
        int r = q >> 4, g = q & 15;
        *(uint4*)&sh2[r * 64 + g * 4] = *(const uint4*)(gAB + (size_t)r * 256 + g * 4);
    }
    __syncthreads();

    int col2 = tid & 31;      // px pair {2col2, 2col2+1}
    int chunk = tid >> 5;
    int r0 = chunk * 32;

    float2 Ac = make_float2(1.f, 1.f), Bc = make_float2(0.f, 0.f);
    #pragma unroll 8
    for (int r = 0; r < 32; r++) {
        uint2 u = *(uint2*)&sh2[(r0 + r) * 64 + col2 * 2];
        float2 p0 = __half22float2(*(__half2*)&u.x);
        float2 p1 = __half22float2(*(__half2*)&u.y);
        Bc.x = fmaf(p0.x, Bc.x, p0.y); Bc.y = fmaf(p1.x, Bc.y, p1.y);
        Ac.x *= p0.x; Ac.y *= p1.x;
    }
    AcS[tid] = Ac; BcS[tid] = Bc;
    __syncthreads();

    float2 h = make_float2(0.f, 0.f);
    for (int k = 0; k < chunk; k++) {
        float2 A = AcS[k * 32 + col2];
        float2 B = BcS[k * 32 + col2];
        h.x = fmaf(A.x, h.x, B.x); h.y = fmaf(A.y, h.y, B.y);
    }

    __half2* S2 = (__half2*)g_sH;
    size_t gb2 = gbase >> 1;
    #pragma unroll 8
    for (int r = 0; r < 32; r++) {
        uint2 u = *(uint2*)&sh2[(r0 + r) * 64 + col2 * 2];
        float2 p0 = __half22float2(*(__half2*)&u.x);
        float2 p1 = __half22float2(*(__half2*)&u.y);
        h.x = fmaf(p0.x, h.x, p0.y); h.y = fmaf(p1.x, h.y, p1.y);
        S2[gb2 + (size_t)(r0 + r) * 128 + col2] = __floats2half2_rn(h.x, h.y);
    }
}

// ============================================================
// K_scanWout: FUSED W-scan + sum(sH) + output GEMM + direct residual store.
// Phase 1 loads interleaved (A,b) pairs from g_AB.
// ============================================================
#define SMEM_SWO (82176)

__device__ __forceinline__ void unpack8h(uint4 u, float* f) {
    float2 t;
    t = __half22float2(*(__half2*)&u.x); f[0] = t.x; f[1] = t.y;
    t = __half22float2(*(__half2*)&u.y); f[2] = t.x; f[3] = t.y;
    t = __half22float2(*(__half2*)&u.z); f[4] = t.x; f[5] = t.y;
    t = __half22float2(*(__half2*)&u.w); f[6] = t.x; f[7] = t.y;
}
__device__ __forceinline__ void unpack8ab(uint4 u0, uint4 u1, float* a, float* b) {
    float2 t;
    t = __half22float2(*(__half2*)&u0.x); a[0] = t.x; b[0] = t.y;
    t = __half22float2(*(__half2*)&u0.y); a[1] = t.x; b[1] = t.y;
    t = __half22float2(*(__half2*)&u0.z); a[2] = t.x; b[2] = t.y;
    t = __half22float2(*(__half2*)&u0.w); a[3] = t.x; b[3] = t.y;
    t = __half22float2(*(__half2*)&u1.x); a[4] = t.x; b[4] = t.y;
    t = __half22float2(*(__half2*)&u1.y); a[5] = t.x; b[5] = t.y;
    t = __half22float2(*(__half2*)&u1.z); a[6] = t.x; b[6] = t.y;
    t = __half22float2(*(__half2*)&u1.w); a[7] = t.x; b[7] = t.y;
}

__global__ __launch_bounds__(512, 2) void kscanWout(
    const float* __restrict__ x,
    const float* __restrict__ b_out,
    const float* __restrict__ gam_p,
    float* __restrict__ out)
{
    extern __shared__ __half sm[];
    __half* sS  = sm;                       // [k=128][px=256] swizzled (64KB)
    __half* sWo = sm + 32768;               // [k=128][co=64] swizzled (16KB)
    float* sbo  = (float*)(sm + 40960);     // [64]

    int tid = threadIdx.x;
    int w = tid >> 5, lane = tid & 31;
    int bi = blockIdx.x >> 8;
    int y  = blockIdx.x & 255;

    {
        const uint4* gW = (const uint4*)g_Woh;
        uint4* sW = (uint4*)sWo;
        #pragma unroll
        for (int q = tid; q < 1024; q += 512) sW[q] = gW[q];
    }
    if (tid < 64) sbo[tid] = b_out[tid];

    // ---- Phase 1: W-scan 8 channels per warp (pipelined loads) ----
    size_t base = ((size_t)(bi * HID + w * 8)) * PLANE + (size_t)y * 256 + lane * 8;
    uint4 uab0 = *(const uint4*)(g_AB + base);
    uint4 uab1 = *(const uint4*)(g_AB + base + 4);
    uint4 us   = *(const uint4*)(g_sH + base);

    #pragma unroll 1
    for (int i = 0; i < 8; i++) {
        float a[8], b[8], s[8];
        unpack8ab(uab0, uab1, a, b);
        unpack8h(us, s);
        if (i < 7) {
            size_t nb = base + (size_t)(i + 1) * PLANE;
            uab0 = *(const uint4*)(g_AB + nb);
            uab1 = *(const uint4*)(g_AB + nb + 4);
            us   = *(const uint4*)(g_sH + nb);
        }

        float Ac = 1.f, Bc = 0.f;
        #pragma unroll
        for (int j = 0; j < 8; j++) {
            Bc = fmaf(a[j], Bc, b[j]);
            Ac = a[j] * Ac;
        }
        #pragma unroll
        for (int d = 1; d < 32; d <<= 1) {
            float Ap = __shfl_up_sync(0xffffffffu, Ac, d);
            float Bp = __shfl_up_sync(0xffffffffu, Bc, d);
            if (lane >= d) {
                Bc = fmaf(Ac, Bp, Bc);
                Ac = Ac * Ap;
            }
        }
        float hin = __shfl_up_sync(0xffffffffu, Bc, 1);
        if (lane == 0) hin = 0.f;

        float h = hin, r[8];
        #pragma unroll
        for (int j = 0; j < 8; j++) {
            h = fmaf(a[j], h, b[j]);
            r[j] = h + s[j];
        }
        int c = w * 8 + i;
        union { uint4 u; __half2 hh[4]; } o;
        o.hh[0] = __floats2half2_rn(r[0], r[1]);
        o.hh[1] = __floats2half2_rn(r[2], r[3]);
        o.hh[2] = __floats2half2_rn(r[4], r[5]);
        o.hh[3] = __floats2half2_rn(r[6], r[7]);
        *(uint4*)&sS[c * 256 + ((lane ^ (c & 7)) << 3)] = o.u;
    }
    __syncthreads();

    // ---- Phase 2: GEMM. Warp w owns m-atom w (16 px), all 8 co-atoms. ----
    float acc[8][4];
    #pragma unroll
    for (int j = 0; j < 8; j++)
        #pragma unroll
        for (int q = 0; q < 4; q++) acc[j][q] = 0.f;

    int kr = lane & 7, sel = lane >> 3;
    #pragma unroll
    for (int kc = 0; kc < 8; kc++) {
        unsigned a[4];
        {
            int krow = kc * 16 + ((sel >> 1) << 3) + kr;
            int mcol = w * 16 + ((sel & 1) << 3);
            unsigned addr = s2u(&sS[krow * 256 + (((mcol >> 3) ^ (krow & 7)) << 3)]);
            ldsm_x4t(a, addr);
        }
        #pragma unroll
        for (int jp = 0; jp < 4; jp++) {
            unsigned b4[4];
            int k = kc * 16 + (lane & 15);
            int cog = jp * 2 + (lane >> 4);
            unsigned addr = s2u(&sWo[k * 64 + ((cog ^ (k & 7)) << 3)]);
            ldsm_x4t(b4, addr);
            mma16816(acc[jp * 2], a, b4);
            mma16816(acc[jp * 2 + 1], a, b4 + 2);
        }
    }

    // ---- direct epilogue ----
    float gam = *gam_p;
    int px = w * 16 + (lane >> 2);
    size_t rowb = (size_t)bi * CIN * PLANE + (size_t)y * 256;
    #pragma unroll
    for (int na = 0; na < 8; na++) {
        int co = na * 8 + (lane & 3) * 2;
        float bo0 = sbo[co], bo1 = sbo[co + 1];
        size_t b0 = rowb + (size_t)co * PLANE + px;
        out[b0]             = fmaf(gam, acc[na][0] + bo0, x[b0]);
        out[b0 + PLANE]     = fmaf(gam, acc[na][1] + bo1, x[b0 + PLANE]);
        out[b0 + 8]         = fmaf(gam, acc[na][2] + bo0, x[b0 + 8]);
        out[b0 + PLANE + 8] = fmaf(gam, acc[na][3] + bo1, x[b0 + PLANE + 8]);
    }
}

// ============================================================
extern "C" void kernel_launch(void* const* d_in, const int* in_sizes, int n_in,
                              void* d_out, int out_size)
{
    const float* x       = (const float*)d_in[0];
    const float* prior   = (const float*)d_in[1];
    const float* W_in    = (const float*)d_in[2];
    const float* b_in    = (const float*)d_in[3];
    const float* W_out   = (const float*)d_in[4];
    const float* b_out   = (const float*)d_in[5];
    const float* W_delta = (const float*)d_in[6];
    const float* b_delta = (const float*)d_in[7];
    const float* W_B     = (const float*)d_in[8];
    const float* b_B     = (const float*)d_in[9];
    const float* A_param = (const float*)d_in[10];
    const float* lam     = (const float*)d_in[11];
    const float* alp     = (const float*)d_in[12];
    const float* gam     = (const float*)d_in[13];
    float* out = (float*)d_out;

    cudaFuncSetAttribute(kproj, cudaFuncAttributeMaxDynamicSharedMemorySize, SMEM_KP);
    cudaFuncSetAttribute(kscanH, cudaFuncAttributeMaxDynamicSharedMemorySize, SMEM_SH);
    cudaFuncSetAttribute(kscanWout, cudaFuncAttributeMaxDynamicSharedMemorySize, SMEM_SWO);

    ksetup<<<130 + NPIX / 256, 256>>>(W_in, b_in, W_delta, b_delta, W_B, b_B,
                                      A_param, W_out, prior, out + OUT2);
    kproj<<<NPIX / (KTILES * 64), 512, SMEM_KP>>>(x, lam, alp);
    kscanH<<<2048, 256, SMEM_SH>>>();
    kscanWout<<<BATCH * 256, 512, SMEM_SWO>>>(x, b_out, gam, out);
}

// round 15
// speedup vs baseline: 1.4006x; 1.0252x over previous
#include <cuda_runtime.h>
#include <cuda_fp16.h>

#define BATCH 4
#define CIN   64
#define HID   128
#define PLANE 65536          // 256*256
#define NPIX  262144         // BATCH*PLANE
#define NELEM 33554432       // BATCH*HID*PLANE
#define OUT2  16777216       // BATCH*CIN*PLANE  (offset of prior_up in d_out)
#define NROWCHUNK 1024       // NPIX / 256

// -------- scratch (static device globals: no allocation allowed) --------
__device__ float  g_ball[384];        // combined biases, index 3c+role
__device__ float  g_Aconst[HID];      // -exp(A_param)
__device__ float  g_prior[NPIX];      // clipped upsampled prior
__device__ __align__(16) __half g_Wh[64 * 384];   // fp16 proj weights [k][n], n=role*128+c, swizzled
__device__ __align__(16) __half g_Woh[128 * 64];  // fp16 W_out [k][co], swizzled
__device__ __align__(16) __half2 g_AB[NELEM];     // interleaved (A_bar, bx) per pixel
__device__ __half g_sH[NELEM];        // H-scan result

__device__ __forceinline__ unsigned s2u(const void* p) {
    return (unsigned)__cvta_generic_to_shared(p);
}
__device__ __forceinline__ void ldsm_x4t(unsigned* r, unsigned addr) {
    asm volatile("ldmatrix.sync.aligned.m8n8.x4.trans.shared.b16 {%0,%1,%2,%3}, [%4];"
                 : "=r"(r[0]), "=r"(r[1]), "=r"(r[2]), "=r"(r[3]) : "r"(addr));
}
__device__ __forceinline__ void ldsm_x2t(unsigned* r, unsigned addr) {
    asm volatile("ldmatrix.sync.aligned.m8n8.x2.trans.shared.b16 {%0,%1}, [%2];"
                 : "=r"(r[0]), "=r"(r[1]) : "r"(addr));
}
__device__ __forceinline__ void mma16816(float* d, const unsigned* a, const unsigned* b) {
    asm volatile("mma.sync.aligned.m16n8k16.row.col.f32.f16.f16.f32 "
                 "{%0,%1,%2,%3},{%4,%5,%6,%7},{%8,%9},{%0,%1,%2,%3};"
                 : "+f"(d[0]), "+f"(d[1]), "+f"(d[2]), "+f"(d[3])
                 : "r"(a[0]), "r"(a[1]), "r"(a[2]), "r"(a[3]), "r"(b[0]), "r"(b[1]));
}

// ============================================================
// K_setup: blocks 0..129 = kpre, blocks 130.. = kprior
// ============================================================
__global__ __launch_bounds__(256) void ksetup(
    const float* __restrict__ W_in, const float* __restrict__ b_in,
    const float* __restrict__ W_delta, const float* __restrict__ b_delta,
    const float* __restrict__ W_B, const float* __restrict__ b_B,
    const float* __restrict__ A_param, const float* __restrict__ W_out,
    const float* __restrict__ prior, float* __restrict__ out2)
{
    if (blockIdx.x < 130) {
        int idx = blockIdx.x * 256 + threadIdx.x;
        if (idx < 384 * 64) {
            int r = idx >> 6, k = idx & 63;
            int c = r / 3, q = r - 3 * c;
            float v;
            if (q == 0) {
                v = W_in[c * 64 + k];
            } else {
                const float* Wm = (q == 1) ? W_delta : W_B;
                float s = 0.f;
                #pragma unroll 4
                for (int j = 0; j < 128; j++) s = fmaf(Wm[c * 128 + j], W_in[j * 64 + k], s);
                v = s;
            }
            int n = q * 128 + c;
            g_Wh[k * 384 + (((n >> 3) ^ (k & 7)) << 3) + (n & 7)] = __float2half(v);
        } else if (idx < 384 * 64 + 384) {
            int r = idx - 384 * 64;
            int c = r / 3, q = r - 3 * c;
            float v;
            if (q == 0) {
                v = b_in[c];
            } else {
                const float* Wm = (q == 1) ? W_delta : W_B;
                const float* bm = (q == 1) ? b_delta : b_B;
                float s = bm[c];
                #pragma unroll 4
                for (int j = 0; j < 128; j++) s = fmaf(Wm[c * 128 + j], b_in[j], s);
                v = s;
            }
            g_ball[r] = v;
        } else if (idx < 384 * 64 + 384 + HID) {
            int c = idx - (384 * 64 + 384);
            g_Aconst[c] = -expf(A_param[c]);
        } else if (idx < 384 * 64 + 384 + HID + 128 * 64) {
            int t = idx - (384 * 64 + 384 + HID);
            int k = t >> 6, co = t & 63;
            g_Woh[k * 64 + (((co >> 3) ^ (k & 7)) << 3) + (co & 7)] =
                __float2half(W_out[co * 128 + k]);
        }
        return;
    }
    int tid = (blockIdx.x - 130) * 256 + threadIdx.x;
    int bi = tid >> 16;
    int hw = tid & 65535;
    int oy = hw >> 8, ox = hw & 255;

    float fy = (float)(oy * 63) / 255.0f;
    float fx = (float)(ox * 63) / 255.0f;
    int y0 = (int)fy; int y1 = min(y0 + 1, 63);
    int x0 = (int)fx; int x1 = min(x0 + 1, 63);
    float wy = fy - (float)y0;
    float wx = fx - (float)x0;

    const float* p = prior + bi * 4096;
    float v00 = p[y0 * 64 + x0], v10 = p[y1 * 64 + x0];
    float v01 = p[y0 * 64 + x1], v11 = p[y1 * 64 + x1];
    float r0 = v00 * (1.f - wy) + v10 * wy;
    float r1 = v01 * (1.f - wy) + v11 * wy;
    float val = r0 * (1.f - wx) + r1 * wx;
    val = fminf(fmaxf(val, -1.f), 1.f);

    g_prior[tid] = val;
    out2[tid] = val;
}

// ============================================================
// K_proj: PERSISTENT (grid=152, grid-stride over 1024 row-chunks).
// Weights/consts staged once per block; sps double-buffered by iteration
// parity; double-buffered sXc, ONE barrier per tile; interleaved half2
// (A,b) epilogue stores.
// smem bytes: sWh 49152 | sXc 2x8192 | sps 2x1024 | sball 1536 | sAc 512
// ============================================================
#define SMEM_KP 69632
#define KTILES  4
#define KPROJ_GRID 152

__global__ __launch_bounds__(512) void kproj(
    const float* __restrict__ x,
    const float* __restrict__ lam_p,
    const float* __restrict__ alp_p)
{
    extern __shared__ char smc[];
    __half* sWh = (__half*)smc;
    __half* sXc = (__half*)(smc + 49152);           // 2 bufs x [c=64][px=64] swizzled
    float*  sps = (float*)(smc + 65536);            // 2 bufs x [256]
    float*  sball = sps + 512;                      // [384]
    float*  sAc   = sball + 384;                    // [128]

    int tid = threadIdx.x;

    // one-time staging
    {
        const uint4* gW = (const uint4*)g_Wh;
        uint4* sW = (uint4*)sWh;
        #pragma unroll
        for (int q = tid; q < 3072; q += 512) sW[q] = gW[q];
    }
    if (tid < 384) sball[tid] = g_ball[tid];
    if (tid < 128) sAc[tid] = g_Aconst[tid];

    // x mapping: q in [0,1024): c = q>>4, seg = q&15 -> 4 floats at px seg*4
    int q0 = tid, q1 = tid + 512;
    int c0 = q0 >> 4, s0 = q0 & 15;
    int c1 = q1 >> 4, s1 = q1 & 15;
    size_t xoff0 = (size_t)c0 * PLANE + s0 * 4;
    size_t xoff1 = (size_t)c1 * PLANE + s1 * 4;

    int w = tid >> 5, lane = tid & 31;
    int wp = w & 7, jw = w >> 3;
    int lr = lane & 15;
    int kr = lane & 7, sel = lane >> 3;
    float lam = *lam_p;
    float alp = *alp_p;

    unsigned aBase = s2u(sXc);

    // first iteration preload
    int pb0 = blockIdx.x;
    {
        int pixB = pb0 * 256;
        const float* xg = x + (size_t)(pixB >> 16) * CIN * PLANE + (pixB & 65535);
        // tile-0 x registers loaded below in loop preamble
    }
    float4 xr0, xr1;
    {
        int pixB = pb0 * 256;
        const float* xg = x + (size_t)(pixB >> 16) * CIN * PLANE + (pixB & 65535);
        xr0 = *(const float4*)(xg + xoff0);
        xr1 = *(const float4*)(xg + xoff1);
    }

    int par = 0;
    #pragma unroll 1
    for (int pb = pb0; pb < NROWCHUNK; pb += KPROJ_GRID, par ^= 1) {
        int pixB = pb * 256;
        int bi = pixB >> 16;
        int hwB = pixB & 65535;
        const float* xg = x + (size_t)bi * CIN * PLANE + hwB;
        float* spsI = sps + par * 256;

        // per-iteration prior tile (parity buffer: no race with prev epilogue)
        if (tid < 256) spsI[tid] = g_prior[pixB + tid];

        #pragma unroll 1
        for (int t = 0; t < KTILES; t++) {
            // store-convert registers -> k-major swizzled sXc buffer (t&1)
            {
                __half* buf = sXc + (t & 1) * 4096;
                __half2 h01 = __floats2half2_rn(xr0.x, xr0.y);
                __half2 h23 = __floats2half2_rn(xr0.z, xr0.w);
                uint2 u; u.x = *(unsigned*)&h01; u.y = *(unsigned*)&h23;
                *(uint2*)&buf[c0 * 64 + (((s0 >> 1) ^ (c0 & 7)) << 3) + (s0 & 1) * 4] = u;
                h01 = __floats2half2_rn(xr1.x, xr1.y);
                h23 = __floats2half2_rn(xr1.z, xr1.w);
                u.x = *(unsigned*)&h01; u.y = *(unsigned*)&h23;
                *(uint2*)&buf[c1 * 64 + (((s1 >> 1) ^ (c1 & 7)) << 3) + (s1 & 1) * 4] = u;
            }
            __syncthreads();   // conv(t) + spsI visible; covers weights on first pass

            // prefetch next tile (or next iteration's tile 0)
            if (t + 1 < KTILES) {
                const float* gt = xg + (t + 1) * 64;
                xr0 = *(const float4*)(gt + xoff0);
                xr1 = *(const float4*)(gt + xoff1);
            } else if (pb + KPROJ_GRID < NROWCHUNK) {
                int npix = (pb + KPROJ_GRID) * 256;
                const float* gt = x + (size_t)(npix >> 16) * CIN * PLANE + (npix & 65535);
                xr0 = *(const float4*)(gt + xoff0);
                xr1 = *(const float4*)(gt + xoff1);
            }

            // mma
            float acc[4][3][4];
            #pragma unroll
            for (int i = 0; i < 4; i++)
                #pragma unroll
                for (int j = 0; j < 3; j++)
                    #pragma unroll
                    for (int q = 0; q < 4; q++) acc[i][j][q] = 0.f;

            unsigned a0 = aBase + (t & 1) * 8192;
            #pragma unroll
            for (int kc = 0; kc < 4; kc++) {
                unsigned a[4][4];
                #pragma unroll
                for (int ma = 0; ma < 4; ma++) {
                    int krow = kc * 16 + ((sel >> 1) << 3) + kr;
                    int mcol = ma * 16 + ((sel & 1) << 3);
                    unsigned addr = a0 + (krow * 64 + (((mcol >> 3) ^ (krow & 7)) << 3)) * 2;
                    ldsm_x4t(a[ma], addr);
                }
                unsigned b[3][2];
                #pragma unroll
                for (int r3 = 0; r3 < 3; r3++) {
                    int na = r3 * 16 + wp * 2 + jw;
                    int k = kc * 16 + lr;
                    int nb = na * 8;
                    unsigned addr = s2u(&sWh[k * 384 + (((nb >> 3) ^ (k & 7)) << 3)]);
                    ldsm_x2t(b[r3], addr);
                }
                #pragma unroll
                for (int ma = 0; ma < 4; ma++)
                    #pragma unroll
                    for (int r3 = 0; r3 < 3; r3++)
                        mma16816(acc[ma][r3], a[ma], b[r3]);
            }

            // epilogue: direct interleaved half2 stores (full 32B sector runs)
            size_t ob = (size_t)bi * HID * PLANE + hwB + t * 64;
            #pragma unroll
            for (int i = 0; i < 2; i++) {
                int c = wp * 16 + jw * 8 + (lane & 3) * 2 + i;
                float bin = sball[3 * c];
                float bdl = sball[3 * c + 1];
                float bbb = sball[3 * c + 2];
                float Ac  = sAc[c];
                size_t cb = ob + (size_t)c * PLANE;
                #pragma unroll
                for (int ma = 0; ma < 4; ma++) {
                    #pragma unroll
                    for (int rr = 0; rr < 2; rr++) {
                        int px = ma * 16 + (lane >> 2) + rr * 8;
                        int idx = rr * 2 + i;
                        float p = spsI[t * 64 + px];
                        float xp   = acc[ma][0][idx] + bin;
                        float dpre = acc[ma][1][idx] + bdl + lam * p;
                        float delta = fmaxf(dpre, 0.f) + __logf(1.f + __expf(-fabsf(dpre)));
                        float bk = (acc[ma][2][idx] + bbb) * (1.f + alp * p);
                        g_AB[cb + px] = __floats2half2_rn(__expf(delta * Ac), delta * bk * xp);
                    }
                }
            }
            // no second barrier: next conv writes the other sXc buffer
        }
    }
}

// ============================================================
// K_scanH: block = 256 rows x 64-col strip of one plane. Single DRAM pass.
// ============================================================
#define SMEM_SH (65536 + 4096)

__global__ __launch_bounds__(256) void kscanH()
{
    extern __shared__ __half2 sh2[];          // sAB[256][64] (A,b) pairs
    float2* AcS  = (float2*)(sh2 + 16384);    // [8][32]
    float2* BcS  = AcS + 256;

    int tid = threadIdx.x;
    int blk = blockIdx.x;
    size_t gbase = (size_t)(blk >> 2) * PLANE + (size_t)(blk & 3) * 64;   // px index
    const __half2* gAB = g_AB + gbase;

    #pragma unroll
    for (int q = tid; q < 4096; q += 256) {
        int r = q >> 4, g = q & 15;
        *(uint4*)&sh2[r * 64 + g * 4] = *(const uint4*)(gAB + (size_t)r * 256 + g * 4);
    }
    __syncthreads();

    int col2 = tid & 31;
    int chunk = tid >> 5;
    int r0 = chunk * 32;

    float2 Ac = make_float2(1.f, 1.f), Bc = make_float2(0.f, 0.f);
    #pragma unroll 8
    for (int r = 0; r < 32; r++) {
        uint2 u = *(uint2*)&sh2[(r0 + r) * 64 + col2 * 2];
        float2 p0 = __half22float2(*(__half2*)&u.x);
        float2 p1 = __half22float2(*(__half2*)&u.y);
        Bc.x = fmaf(p0.x, Bc.x, p0.y); Bc.y = fmaf(p1.x, Bc.y, p1.y);
        Ac.x *= p0.x; Ac.y *= p1.x;
    }
    AcS[tid] = Ac; BcS[tid] = Bc;
    __syncthreads();

    float2 h = make_float2(0.f, 0.f);
    for (int k = 0; k < chunk; k++) {
        float2 A = AcS[k * 32 + col2];
        float2 B = BcS[k * 32 + col2];
        h.x = fmaf(A.x, h.x, B.x); h.y = fmaf(A.y, h.y, B.y);
    }

    __half2* S2 = (__half2*)g_sH;
    size_t gb2 = gbase >> 1;
    #pragma unroll 8
    for (int r = 0; r < 32; r++) {
        uint2 u = *(uint2*)&sh2[(r0 + r) * 64 + col2 * 2];
        float2 p0 = __half22float2(*(__half2*)&u.x);
        float2 p1 = __half22float2(*(__half2*)&u.y);
        h.x = fmaf(p0.x, h.x, p0.y); h.y = fmaf(p1.x, h.y, p1.y);
        S2[gb2 + (size_t)(r0 + r) * 128 + col2] = __floats2half2_rn(h.x, h.y);
    }
}

// ============================================================
// K_scanWout: FUSED W-scan + sum(sH) + output GEMM + direct residual store.
// ============================================================
#define SMEM_SWO (82176)

__device__ __forceinline__ void unpack8h(uint4 u, float* f) {
    float2 t;
    t = __half22float2(*(__half2*)&u.x); f[0] = t.x; f[1] = t.y;
    t = __half22float2(*(__half2*)&u.y); f[2] = t.x; f[3] = t.y;
    t = __half22float2(*(__half2*)&u.z); f[4] = t.x; f[5] = t.y;
    t = __half22float2(*(__half2*)&u.w); f[6] = t.x; f[7] = t.y;
}
__device__ __forceinline__ void unpack8ab(uint4 u0, uint4 u1, float* a, float* b) {
    float2 t;
    t = __half22float2(*(__half2*)&u0.x); a[0] = t.x; b[0] = t.y;
    t = __half22float2(*(__half2*)&u0.y); a[1] = t.x; b[1] = t.y;
    t = __half22float2(*(__half2*)&u0.z); a[2] = t.x; b[2] = t.y;
    t = __half22float2(*(__half2*)&u0.w); a[3] = t.x; b[3] = t.y;
    t = __half22float2(*(__half2*)&u1.x); a[4] = t.x; b[4] = t.y;
    t = __half22float2(*(__half2*)&u1.y); a[5] = t.x; b[5] = t.y;
    t = __half22float2(*(__half2*)&u1.z); a[6] = t.x; b[6] = t.y;
    t = __half22float2(*(__half2*)&u1.w); a[7] = t.x; b[7] = t.y;
}

__global__ __launch_bounds__(512, 2) void kscanWout(
    const float* __restrict__ x,
    const float* __restrict__ b_out,
    const float* __restrict__ gam_p,
    float* __restrict__ out)
{
    extern __shared__ __half sm[];
    __half* sS  = sm;                       // [k=128][px=256] swizzled (64KB)
    __half* sWo = sm + 32768;               // [k=128][co=64] swizzled (16KB)
    float* sbo  = (float*)(sm + 40960);     // [64]

    int tid = threadIdx.x;
    int w = tid >> 5, lane = tid & 31;
    int bi = blockIdx.x >> 8;
    int y  = blockIdx.x & 255;

    {
        const uint4* gW = (const uint4*)g_Woh;
        uint4* sW = (uint4*)sWo;
        #pragma unroll
        for (int q = tid; q < 1024; q += 512) sW[q] = gW[q];
    }
    if (tid < 64) sbo[tid] = b_out[tid];

    // ---- Phase 1: W-scan 8 channels per warp (pipelined loads) ----
    size_t base = ((size_t)(bi * HID + w * 8)) * PLANE + (size_t)y * 256 + lane * 8;
    uint4 uab0 = *(const uint4*)(g_AB + base);
    uint4 uab1 = *(const uint4*)(g_AB + base + 4);
    uint4 us   = *(const uint4*)(g_sH + base);

    #pragma unroll 1
    for (int i = 0; i < 8; i++) {
        float a[8], b[8], s[8];
        unpack8ab(uab0, uab1, a, b);
        unpack8h(us, s);
        if (i < 7) {
            size_t nb = base + (size_t)(i + 1) * PLANE;
            uab0 = *(const uint4*)(g_AB + nb);
            uab1 = *(const uint4*)(g_AB + nb + 4);
            us   = *(const uint4*)(g_sH + nb);
        }

        float Ac = 1.f, Bc = 0.f;
        #pragma unroll
        for (int j = 0; j < 8; j++) {
            Bc = fmaf(a[j], Bc, b[j]);
            Ac = a[j] * Ac;
        }
        #pragma unroll
        for (int d = 1; d < 32; d <<= 1) {
            float Ap = __shfl_up_sync(0xffffffffu, Ac, d);
            float Bp = __shfl_up_sync(0xffffffffu, Bc, d);
            if (lane >= d) {
                Bc = fmaf(Ac, Bp, Bc);
                Ac = Ac * Ap;
            }
        }
        float hin = __shfl_up_sync(0xffffffffu, Bc, 1);
        if (lane == 0) hin = 0.f;

        float h = hin, r[8];
        #pragma unroll
        for (int j = 0; j < 8; j++) {
            h = fmaf(a[j], h, b[j]);
            r[j] = h + s[j];
        }
        int c = w * 8 + i;
        union { uint4 u; __half2 hh[4]; } o;
        o.hh[0] = __floats2half2_rn(r[0], r[1]);
        o.hh[1] = __floats2half2_rn(r[2], r[3]);
        o.hh[2] = __floats2half2_rn(r[4], r[5]);
        o.hh[3] = __floats2half2_rn(r[6], r[7]);
        *(uint4*)&sS[c * 256 + ((lane ^ (c & 7)) << 3)] = o.u;
    }
    __syncthreads();

    // ---- Phase 2: GEMM. Warp w owns m-atom w (16 px), all 8 co-atoms. ----
    float acc[8][4];
    #pragma unroll
    for (int j = 0; j < 8; j++)
        #pragma unroll
        for (int q = 0; q < 4; q++) acc[j][q] = 0.f;

    int kr = lane & 7, sel = lane >> 3;
    #pragma unroll
    for (int kc = 0; kc < 8; kc++) {
        unsigned a[4];
        {
            int krow = kc * 16 + ((sel >> 1) << 3) + kr;
            int mcol = w * 16 + ((sel & 1) << 3);
            unsigned addr = s2u(&sS[krow * 256 + (((mcol >> 3) ^ (krow & 7)) << 3)]);
            ldsm_x4t(a, addr);
        }
        #pragma unroll
        for (int jp = 0; jp < 4; jp++) {
            unsigned b4[4];
            int k = kc * 16 + (lane & 15);
            int cog = jp * 2 + (lane >> 4);
            unsigned addr = s2u(&sWo[k * 64 + ((cog ^ (k & 7)) << 3)]);
            ldsm_x4t(b4, addr);
            mma16816(acc[jp * 2], a, b4);
            mma16816(acc[jp * 2 + 1], a, b4 + 2);
        }
    }

    // ---- direct epilogue ----
    float gam = *gam_p;
    int px = w * 16 + (lane >> 2);
    size_t rowb = (size_t)bi * CIN * PLANE + (size_t)y * 256;
    #pragma unroll
    for (int na = 0; na < 8; na++) {
        int co = na * 8 + (lane & 3) * 2;
        float bo0 = sbo[co], bo1 = sbo[co + 1];
        size_t b0 = rowb + (size_t)co * PLANE + px;
        out[b0]             = fmaf(gam, acc[na][0] + bo0, x[b0]);
        out[b0 + PLANE]     = fmaf(gam, acc[na][1] + bo1, x[b0 + PLANE]);
        out[b0 + 8]         = fmaf(gam, acc[na][2] + bo0, x[b0 + 8]);
        out[b0 + PLANE + 8] = fmaf(gam, acc[na][3] + bo1, x[b0 + PLANE + 8]);
    }
}

// ============================================================
extern "C" void kernel_launch(void* const* d_in, const int* in_sizes, int n_in,
                              void* d_out, int out_size)
{
    const float* x       = (const float*)d_in[0];
    const float* prior   = (const float*)d_in[1];
    const float* W_in    = (const float*)d_in[2];
    const float* b_in    = (const float*)d_in[3];
    const float* W_out   = (const float*)d_in[4];
    const float* b_out   = (const float*)d_in[5];
    const float* W_delta = (const float*)d_in[6];
    const float* b_delta = (const float*)d_in[7];
    const float* W_B     = (const float*)d_in[8];
    const float* b_B     = (const float*)d_in[9];
    const float* A_param = (const float*)d_in[10];
    const float* lam     = (const float*)d_in[11];
    const float* alp     = (const float*)d_in[12];
    const float* gam     = (const float*)d_in[13];
    float* out = (float*)d_out;

    cudaFuncSetAttribute(kproj, cudaFuncAttributeMaxDynamicSharedMemorySize, SMEM_KP);
    cudaFuncSetAttribute(kscanH, cudaFuncAttributeMaxDynamicSharedMemorySize, SMEM_SH);
    cudaFuncSetAttribute(kscanWout, cudaFuncAttributeMaxDynamicSharedMemorySize, SMEM_SWO);

    ksetup<<<130 + NPIX / 256, 256>>>(W_in, b_in, W_delta, b_delta, W_B, b_B,
                                      A_param, W_out, prior, out + OUT2);
    kproj<<<KPROJ_GRID, 512, SMEM_KP>>>(x, lam, alp);
    kscanH<<<2048, 256, SMEM_SH>>>();
    kscanWout<<<BATCH * 256, 512, SMEM_SWO>>>(x, b_out, gam, out);
}

// round 16
// speedup vs baseline: 1.4402x; 1.0283x over previous
#include <cuda_runtime.h>
#include <cuda_fp16.h>

#define BATCH 4
#define CIN   64
#define HID   128
#define PLANE 65536          // 256*256
#define NPIX  262144         // BATCH*PLANE
#define NELEM 33554432       // BATCH*HID*PLANE
#define OUT2  16777216       // BATCH*CIN*PLANE  (offset of prior_up in d_out)
#define NROWCHUNK 1024       // NPIX / 256

// -------- scratch (static device globals: no allocation allowed) --------
__device__ float  g_ball[384];        // combined biases, index 3c+role
__device__ float  g_Aconst[HID];      // -exp(A_param)
__device__ float  g_prior[NPIX];      // clipped upsampled prior
__device__ __align__(16) __half g_Wh[64 * 384];   // fp16 proj weights [k][n], n=role*128+c, swizzled
__device__ __align__(16) __half g_Woh[128 * 64];  // fp16 W_out [k][co], swizzled
__device__ __align__(16) __half2 g_AB[NELEM];     // interleaved (A_bar, bx) per pixel
__device__ __half g_sH[NELEM];        // H-scan result

__device__ __forceinline__ unsigned s2u(const void* p) {
    return (unsigned)__cvta_generic_to_shared(p);
}
__device__ __forceinline__ void ldsm_x4t(unsigned* r, unsigned addr) {
    asm volatile("ldmatrix.sync.aligned.m8n8.x4.trans.shared.b16 {%0,%1,%2,%3}, [%4];"
                 : "=r"(r[0]), "=r"(r[1]), "=r"(r[2]), "=r"(r[3]) : "r"(addr));
}
__device__ __forceinline__ void ldsm_x2t(unsigned* r, unsigned addr) {
    asm volatile("ldmatrix.sync.aligned.m8n8.x2.trans.shared.b16 {%0,%1}, [%2];"
                 : "=r"(r[0]), "=r"(r[1]) : "r"(addr));
}
__device__ __forceinline__ void mma16816(float* d, const unsigned* a, const unsigned* b) {
    asm volatile("mma.sync.aligned.m16n8k16.row.col.f32.f16.f16.f32 "
                 "{%0,%1,%2,%3},{%4,%5,%6,%7},{%8,%9},{%0,%1,%2,%3};"
                 : "+f"(d[0]), "+f"(d[1]), "+f"(d[2]), "+f"(d[3])
                 : "r"(a[0]), "r"(a[1]), "r"(a[2]), "r"(a[3]), "r"(b[0]), "r"(b[1]));
}

// ============================================================
// K_setup: blocks 0..129 = kpre, blocks 130.. = kprior
// ============================================================
__global__ __launch_bounds__(256) void ksetup(
    const float* __restrict__ W_in, const float* __restrict__ b_in,
    const float* __restrict__ W_delta, const float* __restrict__ b_delta,
    const float* __restrict__ W_B, const float* __restrict__ b_B,
    const float* __restrict__ A_param, const float* __restrict__ W_out,
    const float* __restrict__ prior, float* __restrict__ out2)
{
    if (blockIdx.x < 130) {
        int idx = blockIdx.x * 256 + threadIdx.x;
        if (idx < 384 * 64) {
            int r = idx >> 6, k = idx & 63;
            int c = r / 3, q = r - 3 * c;
            float v;
            if (q == 0) {
                v = W_in[c * 64 + k];
            } else {
                const float* Wm = (q == 1) ? W_delta : W_B;
                float s = 0.f;
                #pragma unroll 4
                for (int j = 0; j < 128; j++) s = fmaf(Wm[c * 128 + j], W_in[j * 64 + k], s);
                v = s;
            }
            int n = q * 128 + c;
            g_Wh[k * 384 + (((n >> 3) ^ (k & 7)) << 3) + (n & 7)] = __float2half(v);
        } else if (idx < 384 * 64 + 384) {
            int r = idx - 384 * 64;
            int c = r / 3, q = r - 3 * c;
            float v;
            if (q == 0) {
                v = b_in[c];
            } else {
                const float* Wm = (q == 1) ? W_delta : W_B;
                const float* bm = (q == 1) ? b_delta : b_B;
                float s = bm[c];
                #pragma unroll 4
                for (int j = 0; j < 128; j++) s = fmaf(Wm[c * 128 + j], b_in[j], s);
                v = s;
            }
            g_ball[r] = v;
        } else if (idx < 384 * 64 + 384 + HID) {
            int c = idx - (384 * 64 + 384);
            g_Aconst[c] = -expf(A_param[c]);
        } else if (idx < 384 * 64 + 384 + HID + 128 * 64) {
            int t = idx - (384 * 64 + 384 + HID);
            int k = t >> 6, co = t & 63;
            g_Woh[k * 64 + (((co >> 3) ^ (k & 7)) << 3) + (co & 7)] =
                __float2half(W_out[co * 128 + k]);
        }
        return;
    }
    int tid = (blockIdx.x - 130) * 256 + threadIdx.x;
    int bi = tid >> 16;
    int hw = tid & 65535;
    int oy = hw >> 8, ox = hw & 255;

    float fy = (float)(oy * 63) / 255.0f;
    float fx = (float)(ox * 63) / 255.0f;
    int y0 = (int)fy; int y1 = min(y0 + 1, 63);
    int x0 = (int)fx; int x1 = min(x0 + 1, 63);
    float wy = fy - (float)y0;
    float wx = fx - (float)x0;

    const float* p = prior + bi * 4096;
    float v00 = p[y0 * 64 + x0], v10 = p[y1 * 64 + x0];
    float v01 = p[y0 * 64 + x1], v11 = p[y1 * 64 + x1];
    float r0 = v00 * (1.f - wy) + v10 * wy;
    float r1 = v01 * (1.f - wy) + v11 * wy;
    float val = r0 * (1.f - wx) + r1 * wx;
    val = fminf(fmaxf(val, -1.f), 1.f);

    g_prior[tid] = val;
    out2[tid] = val;
}

// ============================================================
// K_proj: PERSISTENT (grid=152). Same as R14 (passing, 194.3).
// ============================================================
#define SMEM_KP 69632
#define KTILES  4
#define KPROJ_GRID 152

__global__ __launch_bounds__(512) void kproj(
    const float* __restrict__ x,
    const float* __restrict__ lam_p,
    const float* __restrict__ alp_p)
{
    extern __shared__ char smc[];
    __half* sWh = (__half*)smc;
    __half* sXc = (__half*)(smc + 49152);           // 2 bufs x [c=64][px=64] swizzled
    float*  sps = (float*)(smc + 65536);            // 2 bufs x [256]
    float*  sball = sps + 512;                      // [384]
    float*  sAc   = sball + 384;                    // [128]

    int tid = threadIdx.x;

    {
        const uint4* gW = (const uint4*)g_Wh;
        uint4* sW = (uint4*)sWh;
        #pragma unroll
        for (int q = tid; q < 3072; q += 512) sW[q] = gW[q];
    }
    if (tid < 384) sball[tid] = g_ball[tid];
    if (tid < 128) sAc[tid] = g_Aconst[tid];

    int q0 = tid, q1 = tid + 512;
    int c0 = q0 >> 4, s0 = q0 & 15;
    int c1 = q1 >> 4, s1 = q1 & 15;
    size_t xoff0 = (size_t)c0 * PLANE + s0 * 4;
    size_t xoff1 = (size_t)c1 * PLANE + s1 * 4;

    int w = tid >> 5, lane = tid & 31;
    int wp = w & 7, jw = w >> 3;
    int lr = lane & 15;
    int kr = lane & 7, sel = lane >> 3;
    float lam = *lam_p;
    float alp = *alp_p;

    unsigned aBase = s2u(sXc);

    int pb0 = blockIdx.x;
    float4 xr0, xr1;
    {
        int pixB = pb0 * 256;
        const float* xg = x + (size_t)(pixB >> 16) * CIN * PLANE + (pixB & 65535);
        xr0 = *(const float4*)(xg + xoff0);
        xr1 = *(const float4*)(xg + xoff1);
    }

    int par = 0;
    #pragma unroll 1
    for (int pb = pb0; pb < NROWCHUNK; pb += KPROJ_GRID, par ^= 1) {
        int pixB = pb * 256;
        int bi = pixB >> 16;
        int hwB = pixB & 65535;
        const float* xg = x + (size_t)bi * CIN * PLANE + hwB;
        float* spsI = sps + par * 256;

        if (tid < 256) spsI[tid] = g_prior[pixB + tid];

        #pragma unroll 1
        for (int t = 0; t < KTILES; t++) {
            {
                __half* buf = sXc + (t & 1) * 4096;
                __half2 h01 = __floats2half2_rn(xr0.x, xr0.y);
                __half2 h23 = __floats2half2_rn(xr0.z, xr0.w);
                uint2 u; u.x = *(unsigned*)&h01; u.y = *(unsigned*)&h23;
                *(uint2*)&buf[c0 * 64 + (((s0 >> 1) ^ (c0 & 7)) << 3) + (s0 & 1) * 4] = u;
                h01 = __floats2half2_rn(xr1.x, xr1.y);
                h23 = __floats2half2_rn(xr1.z, xr1.w);
                u.x = *(unsigned*)&h01; u.y = *(unsigned*)&h23;
                *(uint2*)&buf[c1 * 64 + (((s1 >> 1) ^ (c1 & 7)) << 3) + (s1 & 1) * 4] = u;
            }
            __syncthreads();

            if (t + 1 < KTILES) {
                const float* gt = xg + (t + 1) * 64;
                xr0 = *(const float4*)(gt + xoff0);
                xr1 = *(const float4*)(gt + xoff1);
            } else if (pb + KPROJ_GRID < NROWCHUNK) {
                int npix = (pb + KPROJ_GRID) * 256;
                const float* gt = x + (size_t)(npix >> 16) * CIN * PLANE + (npix & 65535);
                xr0 = *(const float4*)(gt + xoff0);
                xr1 = *(const float4*)(gt + xoff1);
            }

            float acc[4][3][4];
            #pragma unroll
            for (int i = 0; i < 4; i++)
                #pragma unroll
                for (int j = 0; j < 3; j++)
                    #pragma unroll
                    for (int q = 0; q < 4; q++) acc[i][j][q] = 0.f;

            unsigned a0 = aBase + (t & 1) * 8192;
            #pragma unroll
            for (int kc = 0; kc < 4; kc++) {
                unsigned a[4][4];
                #pragma unroll
                for (int ma = 0; ma < 4; ma++) {
                    int krow = kc * 16 + ((sel >> 1) << 3) + kr;
                    int mcol = ma * 16 + ((sel & 1) << 3);
                    unsigned addr = a0 + (krow * 64 + (((mcol >> 3) ^ (krow & 7)) << 3)) * 2;
                    ldsm_x4t(a[ma], addr);
                }
                unsigned b[3][2];
                #pragma unroll
                for (int r3 = 0; r3 < 3; r3++) {
                    int na = r3 * 16 + wp * 2 + jw;
                    int k = kc * 16 + lr;
                    int nb = na * 8;
                    unsigned addr = s2u(&sWh[k * 384 + (((nb >> 3) ^ (k & 7)) << 3)]);
                    ldsm_x2t(b[r3], addr);
                }
                #pragma unroll
                for (int ma = 0; ma < 4; ma++)
                    #pragma unroll
                    for (int r3 = 0; r3 < 3; r3++)
                        mma16816(acc[ma][r3], a[ma], b[r3]);
            }

            size_t ob = (size_t)bi * HID * PLANE + hwB + t * 64;
            #pragma unroll
            for (int i = 0; i < 2; i++) {
                int c = wp * 16 + jw * 8 + (lane & 3) * 2 + i;
                float bin = sball[3 * c];
                float bdl = sball[3 * c + 1];
                float bbb = sball[3 * c + 2];
                float Ac  = sAc[c];
                size_t cb = ob + (size_t)c * PLANE;
                #pragma unroll
                for (int ma = 0; ma < 4; ma++) {
                    #pragma unroll
                    for (int rr = 0; rr < 2; rr++) {
                        int px = ma * 16 + (lane >> 2) + rr * 8;
                        int idx = rr * 2 + i;
                        float p = spsI[t * 64 + px];
                        float xp   = acc[ma][0][idx] + bin;
                        float dpre = acc[ma][1][idx] + bdl + lam * p;
                        float delta = fmaxf(dpre, 0.f) + __logf(1.f + __expf(-fabsf(dpre)));
                        float bk = (acc[ma][2][idx] + bbb) * (1.f + alp * p);
                        g_AB[cb + px] = __floats2half2_rn(__expf(delta * Ac), delta * bk * xp);
                    }
                }
            }
        }
    }
}

// ============================================================
// K_scanH: REVERSED block order — first blocks read the planes kproj
// wrote last (L2-hot). Otherwise identical to R14.
// ============================================================
#define SMEM_SH (65536 + 4096)

__global__ __launch_bounds__(256) void kscanH()
{
    extern __shared__ __half2 sh2[];          // sAB[256][64] (A,b) pairs
    float2* AcS  = (float2*)(sh2 + 16384);    // [8][32]
    float2* BcS  = AcS + 256;

    int tid = threadIdx.x;
    int blk = gridDim.x - 1 - blockIdx.x;     // REVERSED: hottest L2 data first
    size_t gbase = (size_t)(blk >> 2) * PLANE + (size_t)(blk & 3) * 64;   // px index
    const __half2* gAB = g_AB + gbase;

    #pragma unroll
    for (int q = tid; q < 4096; q += 256) {
        int r = q >> 4, g = q & 15;
        *(uint4*)&sh2[r * 64 + g * 4] = *(const uint4*)(gAB + (size_t)r * 256 + g * 4);
    }
    __syncthreads();

    int col2 = tid & 31;
    int chunk = tid >> 5;
    int r0 = chunk * 32;

    float2 Ac = make_float2(1.f, 1.f), Bc = make_float2(0.f, 0.f);
    #pragma unroll 8
    for (int r = 0; r < 32; r++) {
        uint2 u = *(uint2*)&sh2[(r0 + r) * 64 + col2 * 2];
        float2 p0 = __half22float2(*(__half2*)&u.x);
        float2 p1 = __half22float2(*(__half2*)&u.y);
        Bc.x = fmaf(p0.x, Bc.x, p0.y); Bc.y = fmaf(p1.x, Bc.y, p1.y);
        Ac.x *= p0.x; Ac.y *= p1.x;
    }
    AcS[tid] = Ac; BcS[tid] = Bc;
    __syncthreads();

    float2 h = make_float2(0.f, 0.f);
    for (int k = 0; k < chunk; k++) {
        float2 A = AcS[k * 32 + col2];
        float2 B = BcS[k * 32 + col2];
        h.x = fmaf(A.x, h.x, B.x); h.y = fmaf(A.y, h.y, B.y);
    }

    __half2* S2 = (__half2*)g_sH;
    size_t gb2 = gbase >> 1;
    #pragma unroll 8
    for (int r = 0; r < 32; r++) {
        uint2 u = *(uint2*)&sh2[(r0 + r) * 64 + col2 * 2];
        float2 p0 = __half22float2(*(__half2*)&u.x);
        float2 p1 = __half22float2(*(__half2*)&u.y);
        h.x = fmaf(p0.x, h.x, p0.y); h.y = fmaf(p1.x, h.y, p1.y);
        S2[gb2 + (size_t)(r0 + r) * 128 + col2] = __floats2half2_rn(h.x, h.y);
    }
}

// ============================================================
// K_scanWout: REVERSED block order (freshest sH/AB first). Otherwise R14.
// ============================================================
#define SMEM_SWO (82176)

__device__ __forceinline__ void unpack8h(uint4 u, float* f) {
    float2 t;
    t = __half22float2(*(__half2*)&u.x); f[0] = t.x; f[1] = t.y;
    t = __half22float2(*(__half2*)&u.y); f[2] = t.x; f[3] = t.y;
    t = __half22float2(*(__half2*)&u.z); f[4] = t.x; f[5] = t.y;
    t = __half22float2(*(__half2*)&u.w); f[6] = t.x; f[7] = t.y;
}
__device__ __forceinline__ void unpack8ab(uint4 u0, uint4 u1, float* a, float* b) {
    float2 t;
    t = __half22float2(*(__half2*)&u0.x); a[0] = t.x; b[0] = t.y;
    t = __half22float2(*(__half2*)&u0.y); a[1] = t.x; b[1] = t.y;
    t = __half22float2(*(__half2*)&u0.z); a[2] = t.x; b[2] = t.y;
    t = __half22float2(*(__half2*)&u0.w); a[3] = t.x; b[3] = t.y;
    t = __half22float2(*(__half2*)&u1.x); a[4] = t.x; b[4] = t.y;
    t = __half22float2(*(__half2*)&u1.y); a[5] = t.x; b[5] = t.y;
    t = __half22float2(*(__half2*)&u1.z); a[6] = t.x; b[6] = t.y;
    t = __half22float2(*(__half2*)&u1.w); a[7] = t.x; b[7] = t.y;
}

__global__ __launch_bounds__(512, 2) void kscanWout(
    const float* __restrict__ x,
    const float* __restrict__ b_out,
    const float* __restrict__ gam_p,
    float* __restrict__ out)
{
    extern __shared__ __half sm[];
    __half* sS  = sm;                       // [k=128][px=256] swizzled (64KB)
    __half* sWo = sm + 32768;               // [k=128][co=64] swizzled (16KB)
    float* sbo  = (float*)(sm + 40960);     // [64]

    int tid = threadIdx.x;
    int w = tid >> 5, lane = tid & 31;
    int rb = gridDim.x - 1 - blockIdx.x;    // REVERSED
    int bi = rb >> 8;
    int y  = rb & 255;

    {
        const uint4* gW = (const uint4*)g_Woh;
        uint4* sW = (uint4*)sWo;
        #pragma unroll
        for (int q = tid; q < 1024; q += 512) sW[q] = gW[q];
    }
    if (tid < 64) sbo[tid] = b_out[tid];

    // ---- Phase 1: W-scan 8 channels per warp (pipelined loads) ----
    size_t base = ((size_t)(bi * HID + w * 8)) * PLANE + (size_t)y * 256 + lane * 8;
    uint4 uab0 = *(const uint4*)(g_AB + base);
    uint4 uab1 = *(const uint4*)(g_AB + base + 4);
    uint4 us   = *(const uint4*)(g_sH + base);

    #pragma unroll 1
    for (int i = 0; i < 8; i++) {
        float a[8], b[8], s[8];
        unpack8ab(uab0, uab1, a, b);
        unpack8h(us, s);
        if (i < 7) {
            size_t nb = base + (size_t)(i + 1) * PLANE;
            uab0 = *(const uint4*)(g_AB + nb);
            uab1 = *(const uint4*)(g_AB + nb + 4);
            us   = *(const uint4*)(g_sH + nb);
        }

        float Ac = 1.f, Bc = 0.f;
        #pragma unroll
        for (int j = 0; j < 8; j++) {
            Bc = fmaf(a[j], Bc, b[j]);
            Ac = a[j] * Ac;
        }
        #pragma unroll
        for (int d = 1; d < 32; d <<= 1) {
            float Ap = __shfl_up_sync(0xffffffffu, Ac, d);
            float Bp = __shfl_up_sync(0xffffffffu, Bc, d);
            if (lane >= d) {
                Bc = fmaf(Ac, Bp, Bc);
                Ac = Ac * Ap;
            }
        }
        float hin = __shfl_up_sync(0xffffffffu, Bc, 1);
        if (lane == 0) hin = 0.f;

        float h = hin, r[8];
        #pragma unroll
        for (int j = 0; j < 8; j++) {
            h = fmaf(a[j], h, b[j]);
            r[j] = h + s[j];
        }
        int c = w * 8 + i;
        union { uint4 u; __half2 hh[4]; } o;
        o.hh[0] = __floats2half2_rn(r[0], r[1]);
        o.hh[1] = __floats2half2_rn(r[2], r[3]);
        o.hh[2] = __floats2half2_rn(r[4], r[5]);
        o.hh[3] = __floats2half2_rn(r[6], r[7]);
        *(uint4*)&sS[c * 256 + ((lane ^ (c & 7)) << 3)] = o.u;
    }
    __syncthreads();

    // ---- Phase 2: GEMM. Warp w owns m-atom w (16 px), all 8 co-atoms. ----
    float acc[8][4];
    #pragma unroll
    for (int j = 0; j < 8; j++)
        #pragma unroll
        for (int q = 0; q < 4; q++) acc[j][q] = 0.f;

    int kr = lane & 7, sel = lane >> 3;
    #pragma unroll
    for (int kc = 0; kc < 8; kc++) {
        unsigned a[4];
        {
            int krow = kc * 16 + ((sel >> 1) << 3) + kr;
            int mcol = w * 16 + ((sel & 1) << 3);
            unsigned addr = s2u(&sS[krow * 256 + (((mcol >> 3) ^ (krow & 7)) << 3)]);
            ldsm_x4t(a, addr);
        }
        #pragma unroll
        for (int jp = 0; jp < 4; jp++) {
            unsigned b4[4];
            int k = kc * 16 + (lane & 15);
            int cog = jp * 2 + (lane >> 4);
            unsigned addr = s2u(&sWo[k * 64 + ((cog ^ (k & 7)) << 3)]);
            ldsm_x4t(b4, addr);
            mma16816(acc[jp * 2], a, b4);
            mma16816(acc[jp * 2 + 1], a, b4 + 2);
        }
    }

    // ---- direct epilogue ----
    float gam = *gam_p;
    int px = w * 16 + (lane >> 2);
    size_t rowb = (size_t)bi * CIN * PLANE + (size_t)y * 256;
    #pragma unroll
    for (int na = 0; na < 8; na++) {
        int co = na * 8 + (lane & 3) * 2;
        float bo0 = sbo[co], bo1 = sbo[co + 1];
        size_t b0 = rowb + (size_t)co * PLANE + px;
        out[b0]             = fmaf(gam, acc[na][0] + bo0, x[b0]);
        out[b0 + PLANE]     = fmaf(gam, acc[na][1] + bo1, x[b0 + PLANE]);
        out[b0 + 8]         = fmaf(gam, acc[na][2] + bo0, x[b0 + 8]);
        out[b0 + PLANE + 8] = fmaf(gam, acc[na][3] + bo1, x[b0 + PLANE + 8]);
    }
}

// ============================================================
extern "C" void kernel_launch(void* const* d_in, const int* in_sizes, int n_in,
                              void* d_out, int out_size)
{
    const float* x       = (const float*)d_in[0];
    const float* prior   = (const float*)d_in[1];
    const float* W_in    = (const float*)d_in[2];
    const float* b_in    = (const float*)d_in[3];
    const float* W_out   = (const float*)d_in[4];
    const float* b_out   = (const float*)d_in[5];
    const float* W_delta = (const float*)d_in[6];
    const float* b_delta = (const float*)d_in[7];
    const float* W_B     = (const float*)d_in[8];
    const float* b_B     = (const float*)d_in[9];
    const float* A_param = (const float*)d_in[10];
    const float* lam     = (const float*)d_in[11];
    const float* alp     = (const float*)d_in[12];
    const float* gam     = (const float*)d_in[13];
    float* out = (float*)d_out;

    cudaFuncSetAttribute(kproj, cudaFuncAttributeMaxDynamicSharedMemorySize, SMEM_KP);
    cudaFuncSetAttribute(kscanH, cudaFuncAttributeMaxDynamicSharedMemorySize, SMEM_SH);
    cudaFuncSetAttribute(kscanWout, cudaFuncAttributeMaxDynamicSharedMemorySize, SMEM_SWO);

    ksetup<<<130 + NPIX / 256, 256>>>(W_in, b_in, W_delta, b_delta, W_B, b_B,
                                      A_param, W_out, prior, out + OUT2);
    kproj<<<KPROJ_GRID, 512, SMEM_KP>>>(x, lam, alp);
    kscanH<<<2048, 256, SMEM_SH>>>();
    kscanWout<<<BATCH * 256, 512, SMEM_SWO>>>(x, b_out, gam, out);
}

// round 17
// speedup vs baseline: 1.4757x; 1.0246x over previous
#include <cuda_runtime.h>
#include <cuda_fp16.h>

#define BATCH 4
#define CIN   64
#define HID   128
#define PLANE 65536          // 256*256
#define NPIX  262144         // BATCH*PLANE
#define NELEM 33554432       // BATCH*HID*PLANE
#define OUT2  16777216       // BATCH*CIN*PLANE  (offset of prior_up in d_out)
#define NROWCHUNK 1024       // NPIX / 256

// -------- scratch (static device globals: no allocation allowed) --------
__device__ float  g_ball[384];        // combined biases, index 3c+role
__device__ float  g_Aconst[HID];      // -exp(A_param)
__device__ float  g_prior[NPIX];      // clipped upsampled prior
__device__ __align__(16) __half g_Wh[64 * 384];   // fp16 proj weights [k][n], n=role*128+c, swizzled
__device__ __align__(16) __half g_Woh[128 * 64];  // fp16 W_out [k][co], swizzled
__device__ __align__(16) __half2 g_AB[NELEM];     // interleaved (A_bar, bx) per pixel
__device__ __half g_sH[NELEM];        // H-scan result

__device__ __forceinline__ unsigned s2u(const void* p) {
    return (unsigned)__cvta_generic_to_shared(p);
}
__device__ __forceinline__ void ldsm_x4t(unsigned* r, unsigned addr) {
    asm volatile("ldmatrix.sync.aligned.m8n8.x4.trans.shared.b16 {%0,%1,%2,%3}, [%4];"
                 : "=r"(r[0]), "=r"(r[1]), "=r"(r[2]), "=r"(r[3]) : "r"(addr));
}
__device__ __forceinline__ void ldsm_x2t(unsigned* r, unsigned addr) {
    asm volatile("ldmatrix.sync.aligned.m8n8.x2.trans.shared.b16 {%0,%1}, [%2];"
                 : "=r"(r[0]), "=r"(r[1]) : "r"(addr));
}
__device__ __forceinline__ void mma16816(float* d, const unsigned* a, const unsigned* b) {
    asm volatile("mma.sync.aligned.m16n8k16.row.col.f32.f16.f16.f32 "
                 "{%0,%1,%2,%3},{%4,%5,%6,%7},{%8,%9},{%0,%1,%2,%3};"
                 : "+f"(d[0]), "+f"(d[1]), "+f"(d[2]), "+f"(d[3])
                 : "r"(a[0]), "r"(a[1]), "r"(a[2]), "r"(a[3]), "r"(b[0]), "r"(b[1]));
}

// ============================================================
// K_setup: blocks 0..129 = kpre, blocks 130.. = kprior
// ============================================================
__global__ __launch_bounds__(256) void ksetup(
    const float* __restrict__ W_in, const float* __restrict__ b_in,
    const float* __restrict__ W_delta, const float* __restrict__ b_delta,
    const float* __restrict__ W_B, const float* __restrict__ b_B,
    const float* __restrict__ A_param, const float* __restrict__ W_out,
    const float* __restrict__ prior, float* __restrict__ out2)
{
    if (blockIdx.x < 130) {
        int idx = blockIdx.x * 256 + threadIdx.x;
        if (idx < 384 * 64) {
            int r = idx >> 6, k = idx & 63;
            int c = r / 3, q = r - 3 * c;
            float v;
            if (q == 0) {
                v = W_in[c * 64 + k];
            } else {
                const float* Wm = (q == 1) ? W_delta : W_B;
                float s = 0.f;
                #pragma unroll 4
                for (int j = 0; j < 128; j++) s = fmaf(Wm[c * 128 + j], W_in[j * 64 + k], s);
                v = s;
            }
            int n = q * 128 + c;
            g_Wh[k * 384 + (((n >> 3) ^ (k & 7)) << 3) + (n & 7)] = __float2half(v);
        } else if (idx < 384 * 64 + 384) {
            int r = idx - 384 * 64;
            int c = r / 3, q = r - 3 * c;
            float v;
            if (q == 0) {
                v = b_in[c];
            } else {
                const float* Wm = (q == 1) ? W_delta : W_B;
                const float* bm = (q == 1) ? b_delta : b_B;
                float s = bm[c];
                #pragma unroll 4
                for (int j = 0; j < 128; j++) s = fmaf(Wm[c * 128 + j], b_in[j], s);
                v = s;
            }
            g_ball[r] = v;
        } else if (idx < 384 * 64 + 384 + HID) {
            int c = idx - (384 * 64 + 384);
            g_Aconst[c] = -expf(A_param[c]);
        } else if (idx < 384 * 64 + 384 + HID + 128 * 64) {
            int t = idx - (384 * 64 + 384 + HID);
            int k = t >> 6, co = t & 63;
            g_Woh[k * 64 + (((co >> 3) ^ (k & 7)) << 3) + (co & 7)] =
                __float2half(W_out[co * 128 + k]);
        }
        return;
    }
    int tid = (blockIdx.x - 130) * 256 + threadIdx.x;
    int bi = tid >> 16;
    int hw = tid & 65535;
    int oy = hw >> 8, ox = hw & 255;

    float fy = (float)(oy * 63) / 255.0f;
    float fx = (float)(ox * 63) / 255.0f;
    int y0 = (int)fy; int y1 = min(y0 + 1, 63);
    int x0 = (int)fx; int x1 = min(x0 + 1, 63);
    float wy = fy - (float)y0;
    float wx = fx - (float)x0;

    const float* p = prior + bi * 4096;
    float v00 = p[y0 * 64 + x0], v10 = p[y1 * 64 + x0];
    float v01 = p[y0 * 64 + x1], v11 = p[y1 * 64 + x1];
    float r0 = v00 * (1.f - wy) + v10 * wy;
    float r1 = v01 * (1.f - wy) + v11 * wy;
    float val = r0 * (1.f - wx) + r1 * wx;
    val = fminf(fmaxf(val, -1.f), 1.f);

    g_prior[tid] = val;
    out2[tid] = val;
}

// ============================================================
// K_proj: PERSISTENT (grid=152). Epilogue with hoisted per-px terms.
// ============================================================
#define SMEM_KP 69632
#define KTILES  4
#define KPROJ_GRID 152

__global__ __launch_bounds__(512) void kproj(
    const float* __restrict__ x,
    const float* __restrict__ lam_p,
    const float* __restrict__ alp_p)
{
    extern __shared__ char smc[];
    __half* sWh = (__half*)smc;
    __half* sXc = (__half*)(smc + 49152);           // 2 bufs x [c=64][px=64] swizzled
    float*  sps = (float*)(smc + 65536);            // 2 bufs x [256]
    float*  sball = sps + 512;                      // [384]
    float*  sAc   = sball + 384;                    // [128]

    int tid = threadIdx.x;

    {
        const uint4* gW = (const uint4*)g_Wh;
        uint4* sW = (uint4*)sWh;
        #pragma unroll
        for (int q = tid; q < 3072; q += 512) sW[q] = gW[q];
    }
    if (tid < 384) sball[tid] = g_ball[tid];
    if (tid < 128) sAc[tid] = g_Aconst[tid];

    int q0 = tid, q1 = tid + 512;
    int c0 = q0 >> 4, s0 = q0 & 15;
    int c1 = q1 >> 4, s1 = q1 & 15;
    size_t xoff0 = (size_t)c0 * PLANE + s0 * 4;
    size_t xoff1 = (size_t)c1 * PLANE + s1 * 4;

    int w = tid >> 5, lane = tid & 31;
    int wp = w & 7, jw = w >> 3;
    int lr = lane & 15;
    int kr = lane & 7, sel = lane >> 3;
    float lam = *lam_p;
    float alp = *alp_p;

    unsigned aBase = s2u(sXc);

    int pb0 = blockIdx.x;
    float4 xr0, xr1;
    {
        int pixB = pb0 * 256;
        const float* xg = x + (size_t)(pixB >> 16) * CIN * PLANE + (pixB & 65535);
        xr0 = *(const float4*)(xg + xoff0);
        xr1 = *(const float4*)(xg + xoff1);
    }

    int par = 0;
    #pragma unroll 1
    for (int pb = pb0; pb < NROWCHUNK; pb += KPROJ_GRID, par ^= 1) {
        int pixB = pb * 256;
        int bi = pixB >> 16;
        int hwB = pixB & 65535;
        const float* xg = x + (size_t)bi * CIN * PLANE + hwB;
        float* spsI = sps + par * 256;

        if (tid < 256) spsI[tid] = g_prior[pixB + tid];

        #pragma unroll 1
        for (int t = 0; t < KTILES; t++) {
            {
                __half* buf = sXc + (t & 1) * 4096;
                __half2 h01 = __floats2half2_rn(xr0.x, xr0.y);
                __half2 h23 = __floats2half2_rn(xr0.z, xr0.w);
                uint2 u; u.x = *(unsigned*)&h01; u.y = *(unsigned*)&h23;
                *(uint2*)&buf[c0 * 64 + (((s0 >> 1) ^ (c0 & 7)) << 3) + (s0 & 1) * 4] = u;
                h01 = __floats2half2_rn(xr1.x, xr1.y);
                h23 = __floats2half2_rn(xr1.z, xr1.w);
                u.x = *(unsigned*)&h01; u.y = *(unsigned*)&h23;
                *(uint2*)&buf[c1 * 64 + (((s1 >> 1) ^ (c1 & 7)) << 3) + (s1 & 1) * 4] = u;
            }
            __syncthreads();

            if (t + 1 < KTILES) {
                const float* gt = xg + (t + 1) * 64;
                xr0 = *(const float4*)(gt + xoff0);
                xr1 = *(const float4*)(gt + xoff1);
            } else if (pb + KPROJ_GRID < NROWCHUNK) {
                int npix = (pb + KPROJ_GRID) * 256;
                const float* gt = x + (size_t)(npix >> 16) * CIN * PLANE + (npix & 65535);
                xr0 = *(const float4*)(gt + xoff0);
                xr1 = *(const float4*)(gt + xoff1);
            }

            float acc[4][3][4];
            #pragma unroll
            for (int i = 0; i < 4; i++)
                #pragma unroll
                for (int j = 0; j < 3; j++)
                    #pragma unroll
                    for (int q = 0; q < 4; q++) acc[i][j][q] = 0.f;

            unsigned a0 = aBase + (t & 1) * 8192;
            #pragma unroll
            for (int kc = 0; kc < 4; kc++) {
                unsigned a[4][4];
                #pragma unroll
                for (int ma = 0; ma < 4; ma++) {
                    int krow = kc * 16 + ((sel >> 1) << 3) + kr;
                    int mcol = ma * 16 + ((sel & 1) << 3);
                    unsigned addr = a0 + (krow * 64 + (((mcol >> 3) ^ (krow & 7)) << 3)) * 2;
                    ldsm_x4t(a[ma], addr);
                }
                unsigned b[3][2];
                #pragma unroll
                for (int r3 = 0; r3 < 3; r3++) {
                    int na = r3 * 16 + wp * 2 + jw;
                    int k = kc * 16 + lr;
                    int nb = na * 8;
                    unsigned addr = s2u(&sWh[k * 384 + (((nb >> 3) ^ (k & 7)) << 3)]);
                    ldsm_x2t(b[r3], addr);
                }
                #pragma unroll
                for (int ma = 0; ma < 4; ma++)
                    #pragma unroll
                    for (int r3 = 0; r3 < 3; r3++)
                        mma16816(acc[ma][r3], a[ma], b[r3]);
            }

            // hoisted per-px terms (identical expressions -> bit-identical)
            float lampx[8], alppx[8];
            #pragma unroll
            for (int ma = 0; ma < 4; ma++)
                #pragma unroll
                for (int rr = 0; rr < 2; rr++) {
                    float p = spsI[t * 64 + ma * 16 + (lane >> 2) + rr * 8];
                    lampx[ma * 2 + rr] = lam * p;
                    alppx[ma * 2 + rr] = 1.f + alp * p;
                }

            size_t ob = (size_t)bi * HID * PLANE + hwB + t * 64;
            #pragma unroll
            for (int i = 0; i < 2; i++) {
                int c = wp * 16 + jw * 8 + (lane & 3) * 2 + i;
                float bin = sball[3 * c];
                float bdl = sball[3 * c + 1];
                float bbb = sball[3 * c + 2];
                float Ac  = sAc[c];
                size_t cb = ob + (size_t)c * PLANE;
                #pragma unroll
                for (int ma = 0; ma < 4; ma++) {
                    #pragma unroll
                    for (int rr = 0; rr < 2; rr++) {
                        int px = ma * 16 + (lane >> 2) + rr * 8;
                        int idx = rr * 2 + i;
                        int pj = ma * 2 + rr;
                        float xp   = acc[ma][0][idx] + bin;
                        float dpre = acc[ma][1][idx] + bdl + lampx[pj];
                        float delta = fmaxf(dpre, 0.f) + __logf(1.f + __expf(-fabsf(dpre)));
                        float bk = (acc[ma][2][idx] + bbb) * alppx[pj];
                        g_AB[cb + px] = __floats2half2_rn(__expf(delta * Ac), delta * bk * xp);
                    }
                }
            }
        }
    }
}

// ============================================================
// K_scanH: REVERSED block order (reads kproj's freshest planes first).
// ============================================================
#define SMEM_SH (65536 + 4096)

__global__ __launch_bounds__(256) void kscanH()
{
    extern __shared__ __half2 sh2[];          // sAB[256][64] (A,b) pairs
    float2* AcS  = (float2*)(sh2 + 16384);    // [8][32]
    float2* BcS  = AcS + 256;

    int tid = threadIdx.x;
    int blk = gridDim.x - 1 - blockIdx.x;     // REVERSED: hottest L2 data first
    size_t gbase = (size_t)(blk >> 2) * PLANE + (size_t)(blk & 3) * 64;   // px index
    const __half2* gAB = g_AB + gbase;

    #pragma unroll
    for (int q = tid; q < 4096; q += 256) {
        int r = q >> 4, g = q & 15;
        *(uint4*)&sh2[r * 64 + g * 4] = *(const uint4*)(gAB + (size_t)r * 256 + g * 4);
    }
    __syncthreads();

    int col2 = tid & 31;
    int chunk = tid >> 5;
    int r0 = chunk * 32;

    float2 Ac = make_float2(1.f, 1.f), Bc = make_float2(0.f, 0.f);
    #pragma unroll 8
    for (int r = 0; r < 32; r++) {
        uint2 u = *(uint2*)&sh2[(r0 + r) * 64 + col2 * 2];
        float2 p0 = __half22float2(*(__half2*)&u.x);
        float2 p1 = __half22float2(*(__half2*)&u.y);
        Bc.x = fmaf(p0.x, Bc.x, p0.y); Bc.y = fmaf(p1.x, Bc.y, p1.y);
        Ac.x *= p0.x; Ac.y *= p1.x;
    }
    AcS[tid] = Ac; BcS[tid] = Bc;
    __syncthreads();

    float2 h = make_float2(0.f, 0.f);
    for (int k = 0; k < chunk; k++) {
        float2 A = AcS[k * 32 + col2];
        float2 B = BcS[k * 32 + col2];
        h.x = fmaf(A.x, h.x, B.x); h.y = fmaf(A.y, h.y, B.y);
    }

    __half2* S2 = (__half2*)g_sH;
    size_t gb2 = gbase >> 1;
    #pragma unroll 8
    for (int r = 0; r < 32; r++) {
        uint2 u = *(uint2*)&sh2[(r0 + r) * 64 + col2 * 2];
        float2 p0 = __half22float2(*(__half2*)&u.x);
        float2 p1 = __half22float2(*(__half2*)&u.y);
        h.x = fmaf(p0.x, h.x, p0.y); h.y = fmaf(p1.x, h.y, p1.y);
        S2[gb2 + (size_t)(r0 + r) * 128 + col2] = __floats2half2_rn(h.x, h.y);
    }
}

// ============================================================
// K_scanWout: FORWARD order (kscanH reversed finishes on LOW planes ->
// forward consumer starts on L2-hot sH/AB). Otherwise identical.
// ============================================================
#define SMEM_SWO (82176)

__device__ __forceinline__ void unpack8h(uint4 u, float* f) {
    float2 t;
    t = __half22float2(*(__half2*)&u.x); f[0] = t.x; f[1] = t.y;
    t = __half22float2(*(__half2*)&u.y); f[2] = t.x; f[3] = t.y;
    t = __half22float2(*(__half2*)&u.z); f[4] = t.x; f[5] = t.y;
    t = __half22float2(*(__half2*)&u.w); f[6] = t.x; f[7] = t.y;
}
__device__ __forceinline__ void unpack8ab(uint4 u0, uint4 u1, float* a, float* b) {
    float2 t;
    t = __half22float2(*(__half2*)&u0.x); a[0] = t.x; b[0] = t.y;
    t = __half22float2(*(__half2*)&u0.y); a[1] = t.x; b[1] = t.y;
    t = __half22float2(*(__half2*)&u0.z); a[2] = t.x; b[2] = t.y;
    t = __half22float2(*(__half2*)&u0.w); a[3] = t.x; b[3] = t.y;
    t = __half22float2(*(__half2*)&u1.x); a[4] = t.x; b[4] = t.y;
    t = __half22float2(*(__half2*)&u1.y); a[5] = t.x; b[5] = t.y;
    t = __half22float2(*(__half2*)&u1.z); a[6] = t.x; b[6] = t.y;
    t = __half22float2(*(__half2*)&u1.w); a[7] = t.x; b[7] = t.y;
}

__global__ __launch_bounds__(512, 2) void kscanWout(
    const float* __restrict__ x,
    const float* __restrict__ b_out,
    const float* __restrict__ gam_p,
    float* __restrict__ out)
{
    extern __shared__ __half sm[];
    __half* sS  = sm;                       // [k=128][px=256] swizzled (64KB)
    __half* sWo = sm + 32768;               // [k=128][co=64] swizzled (16KB)
    float* sbo  = (float*)(sm + 40960);     // [64]

    int tid = threadIdx.x;
    int w = tid >> 5, lane = tid & 31;
    int bi = blockIdx.x >> 8;               // FORWARD
    int y  = blockIdx.x & 255;

    {
        const uint4* gW = (const uint4*)g_Woh;
        uint4* sW = (uint4*)sWo;
        #pragma unroll
        for (int q = tid; q < 1024; q += 512) sW[q] = gW[q];
    }
    if (tid < 64) sbo[tid] = b_out[tid];

    // ---- Phase 1: W-scan 8 channels per warp (pipelined loads) ----
    size_t base = ((size_t)(bi * HID + w * 8)) * PLANE + (size_t)y * 256 + lane * 8;
    uint4 uab0 = *(const uint4*)(g_AB + base);
    uint4 uab1 = *(const uint4*)(g_AB + base + 4);
    uint4 us   = *(const uint4*)(g_sH + base);

    #pragma unroll 1
    for (int i = 0; i < 8; i++) {
        float a[8], b[8], s[8];
        unpack8ab(uab0, uab1, a, b);
        unpack8h(us, s);
        if (i < 7) {
            size_t nb = base + (size_t)(i + 1) * PLANE;
            uab0 = *(const uint4*)(g_AB + nb);
            uab1 = *(const uint4*)(g_AB + nb + 4);
            us   = *(const uint4*)(g_sH + nb);
        }

        float Ac = 1.f, Bc = 0.f;
        #pragma unroll
        for (int j = 0; j < 8; j++) {
            Bc = fmaf(a[j], Bc, b[j]);
            Ac = a[j] * Ac;
        }
        #pragma unroll
        for (int d = 1; d < 32; d <<= 1) {
            float Ap = __shfl_up_sync(0xffffffffu, Ac, d);
            float Bp = __shfl_up_sync(0xffffffffu, Bc, d);
            if (lane >= d) {
                Bc = fmaf(Ac, Bp, Bc);
                Ac = Ac * Ap;
            }
        }
        float hin = __shfl_up_sync(0xffffffffu, Bc, 1);
        if (lane == 0) hin = 0.f;

        float h = hin, r[8];
        #pragma unroll
        for (int j = 0; j < 8; j++) {
            h = fmaf(a[j], h, b[j]);
            r[j] = h + s[j];
        }
        int c = w * 8 + i;
        union { uint4 u; __half2 hh[4]; } o;
        o.hh[0] = __floats2half2_rn(r[0], r[1]);
        o.hh[1] = __floats2half2_rn(r[2], r[3]);
        o.hh[2] = __floats2half2_rn(r[4], r[5]);
        o.hh[3] = __floats2half2_rn(r[6], r[7]);
        *(uint4*)&sS[c * 256 + ((lane ^ (c & 7)) << 3)] = o.u;
    }
    __syncthreads();

    // ---- Phase 2: GEMM. Warp w owns m-atom w (16 px), all 8 co-atoms. ----
    float acc[8][4];
    #pragma unroll
    for (int j = 0; j < 8; j++)
        #pragma unroll
        for (int q = 0; q < 4; q++) acc[j][q] = 0.f;

    int kr = lane & 7, sel = lane >> 3;
    #pragma unroll
    for (int kc = 0; kc < 8; kc++) {
        unsigned a[4];
        {
            int krow = kc * 16 + ((sel >> 1) << 3) + kr;
            int mcol = w * 16 + ((sel & 1) << 3);
            unsigned addr = s2u(&sS[krow * 256 + (((mcol >> 3) ^ (krow & 7)) << 3)]);
            ldsm_x4t(a, addr);
        }
        #pragma unroll
        for (int jp = 0; jp < 4; jp++) {
            unsigned b4[4];
            int k = kc * 16 + (lane & 15);
            int cog = jp * 2 + (lane >> 4);
            unsigned addr = s2u(&sWo[k * 64 + ((cog ^ (k & 7)) << 3)]);
            ldsm_x4t(b4, addr);
            mma16816(acc[jp * 2], a, b4);
            mma16816(acc[jp * 2 + 1], a, b4 + 2);
        }
    }

    // ---- direct epilogue ----
    float gam = *gam_p;
    int px = w * 16 + (lane >> 2);
    size_t rowb = (size_t)bi * CIN * PLANE + (size_t)y * 256;
    #pragma unroll
    for (int na = 0; na < 8; na++) {
        int co = na * 8 + (lane & 3) * 2;
        float bo0 = sbo[co], bo1 = sbo[co + 1];
        size_t b0 = rowb + (size_t)co * PLANE + px;
        out[b0]             = fmaf(gam, acc[na][0] + bo0, x[b0]);
        out[b0 + PLANE]     = fmaf(gam, acc[na][1] + bo1, x[b0 + PLANE]);
        out[b0 + 8]         = fmaf(gam, acc[na][2] + bo0, x[b0 + 8]);
        out[b0 + PLANE + 8] = fmaf(gam, acc[na][3] + bo1, x[b0 + PLANE + 8]);
    }
}

// ============================================================
extern "C" void kernel_launch(void* const* d_in, const int* in_sizes, int n_in,
                              void* d_out, int out_size)
{
    const float* x       = (const float*)d_in[0];
    const float* prior   = (const float*)d_in[1];
    const float* W_in    = (const float*)d_in[2];
    const float* b_in    = (const float*)d_in[3];
    const float* W_out   = (const float*)d_in[4];
    const float* b_out   = (const float*)d_in[5];
    const float* W_delta = (const float*)d_in[6];
    const float* b_delta = (const float*)d_in[7];
    const float* W_B     = (const float*)d_in[8];
    const float* b_B     = (const float*)d_in[9];
    const float* A_param = (const float*)d_in[10];
    const float* lam     = (const float*)d_in[11];
    const float* alp     = (const float*)d_in[12];
    const float* gam     = (const float*)d_in[13];
    float* out = (float*)d_out;

    cudaFuncSetAttribute(kproj, cudaFuncAttributeMaxDynamicSharedMemorySize, SMEM_KP);
    cudaFuncSetAttribute(kscanH, cudaFuncAttributeMaxDynamicSharedMemorySize, SMEM_SH);
    cudaFuncSetAttribute(kscanWout, cudaFuncAttributeMaxDynamicSharedMemorySize, SMEM_SWO);

    ksetup<<<130 + NPIX / 256, 256>>>(W_in, b_in, W_delta, b_delta, W_B, b_B,
                                      A_param, W_out, prior, out + OUT2);
    kproj<<<KPROJ_GRID, 512, SMEM_KP>>>(x, lam, alp);
    kscanH<<<2048, 256, SMEM_SH>>>();
    kscanWout<<<BATCH * 256, 512, SMEM_SWO>>>(x, b_out, gam, out);
}